// round 11
// baseline (speedup 1.0000x reference)
#include <cuda_runtime.h>
#include <math_constants.h>

#define NUM_HEADS 32
#define NUM_KV    8
#define HEAD_DIM  128
#define HIDDEN    4096
#define BSZ       32
#define MAX_SEQ   4096
#define GROUP     4
#define G2        2            // heads per attention block (GROUP split in 2)
#define QKV_OUT   6144
#define CHUNK     128
#define NCHUNK    32
// attention scale * log2(e): softmax in exp2 domain
#define QSCALE    (0.08838834764831845f * 1.4426950408889634f)

// GEMM tiling: BM=512, BK=8, 256 threads, per-thread 8m x 8b
#define GBM 512
#define GBK 8
#define WST 516
#define XST 36
#define QKV_SPLIT 24
#define WO_SPLIT  36

// ---------------- scratch (no allocs allowed) ----------------
__device__ float g_qkv [BSZ * QKV_OUT];
__device__ float g_attn[BSZ * NUM_HEADS * HEAD_DIM];
__device__ float g_part[QKV_SPLIT * BSZ * QKV_OUT];
__device__ float g_po  [BSZ * NUM_KV * GROUP * NCHUNK * HEAD_DIM];
__device__ float g_pml [BSZ * NUM_KV * GROUP * NCHUNK * 2];

// packed fp32x2 ops (Blackwell)
__device__ __forceinline__ void fma2(unsigned long long& d,
                                     unsigned long long a,
                                     unsigned long long b) {
    asm("fma.rn.f32x2 %0, %1, %2, %0;" : "+l"(d) : "l"(a), "l"(b));
}
__device__ __forceinline__ unsigned long long dup2(float v) {
    unsigned long long r;
    asm("mov.b64 %0, {%1, %1};" : "=l"(r) : "f"(v));
    return r;
}

// ---------------------------------------------------------------
// Split-K GEMM writing per-split partials (R4-measured form, unchanged)
// ---------------------------------------------------------------
__global__ void __launch_bounds__(256, 2)
gemm8x8_kernel(const float* __restrict__ W, const float* __restrict__ x,
               float* __restrict__ part, int M, int K, int nsplit)
{
    __shared__ __align__(16) float Ws[2][GBK][WST];
    __shared__ __align__(16) float Xs[2][GBK][XST];

    const int m0    = blockIdx.x * GBM;
    const int tot   = K / GBK;
    const int tile0 = (blockIdx.y * tot) / nsplit;
    const int tile1 = ((blockIdx.y + 1) * tot) / nsplit;

    const int t   = threadIdx.x;
    const int ty  = t >> 2;
    const int tx  = t & 3;
    const int r0  = t >> 1;
    const int wkv = t & 1;
    const int xb  = t & 31;
    const int xkv = t >> 5;

    float4 wst[4];
    float4 xst;

    {
        const float* wp = W + (size_t)(m0 + r0) * K + (size_t)tile0 * GBK + wkv * 4;
        #pragma unroll
        for (int i = 0; i < 4; i++)
            wst[i] = *reinterpret_cast<const float4*>(wp + (size_t)i * 128 * K);
        if (t < 64)
            xst = *reinterpret_cast<const float4*>(x + (size_t)xb * K + (size_t)tile0 * GBK + xkv * 4);

        #pragma unroll
        for (int i = 0; i < 4; i++) {
            int r = r0 + i * 128;
            Ws[0][wkv*4+0][r] = wst[i].x;
            Ws[0][wkv*4+1][r] = wst[i].y;
            Ws[0][wkv*4+2][r] = wst[i].z;
            Ws[0][wkv*4+3][r] = wst[i].w;
        }
        if (t < 64) {
            Xs[0][xkv*4+0][xb] = xst.x;
            Xs[0][xkv*4+1][xb] = xst.y;
            Xs[0][xkv*4+2][xb] = xst.z;
            Xs[0][xkv*4+3][xb] = xst.w;
        }
    }
    __syncthreads();

    unsigned long long acc[4][8];
    #pragma unroll
    for (int i = 0; i < 4; i++)
        #pragma unroll
        for (int j = 0; j < 8; j++) acc[i][j] = 0ull;

    int p = 0;
    for (int tile = tile0; tile < tile1; tile++) {
        const bool has_next = (tile + 1 < tile1);
        if (has_next) {
            const float* wp = W + (size_t)(m0 + r0) * K + (size_t)(tile + 1) * GBK + wkv * 4;
            #pragma unroll
            for (int i = 0; i < 4; i++)
                wst[i] = *reinterpret_cast<const float4*>(wp + (size_t)i * 128 * K);
            if (t < 64)
                xst = *reinterpret_cast<const float4*>(x + (size_t)xb * K + (size_t)(tile + 1) * GBK + xkv * 4);
        }

        #pragma unroll
        for (int k = 0; k < GBK; k++) {
            ulonglong2 w01 = *reinterpret_cast<const ulonglong2*>(&Ws[p][k][ty * 8]);
            ulonglong2 w23 = *reinterpret_cast<const ulonglong2*>(&Ws[p][k][ty * 8 + 4]);
            float4 xa = *reinterpret_cast<const float4*>(&Xs[p][k][tx * 8]);
            float4 xc = *reinterpret_cast<const float4*>(&Xs[p][k][tx * 8 + 4]);
            unsigned long long xd;
            xd = dup2(xa.x);
            fma2(acc[0][0], w01.x, xd); fma2(acc[1][0], w01.y, xd);
            fma2(acc[2][0], w23.x, xd); fma2(acc[3][0], w23.y, xd);
            xd = dup2(xa.y);
            fma2(acc[0][1], w01.x, xd); fma2(acc[1][1], w01.y, xd);
            fma2(acc[2][1], w23.x, xd); fma2(acc[3][1], w23.y, xd);
            xd = dup2(xa.z);
            fma2(acc[0][2], w01.x, xd); fma2(acc[1][2], w01.y, xd);
            fma2(acc[2][2], w23.x, xd); fma2(acc[3][2], w23.y, xd);
            xd = dup2(xa.w);
            fma2(acc[0][3], w01.x, xd); fma2(acc[1][3], w01.y, xd);
            fma2(acc[2][3], w23.x, xd); fma2(acc[3][3], w23.y, xd);
            xd = dup2(xc.x);
            fma2(acc[0][4], w01.x, xd); fma2(acc[1][4], w01.y, xd);
            fma2(acc[2][4], w23.x, xd); fma2(acc[3][4], w23.y, xd);
            xd = dup2(xc.y);
            fma2(acc[0][5], w01.x, xd); fma2(acc[1][5], w01.y, xd);
            fma2(acc[2][5], w23.x, xd); fma2(acc[3][5], w23.y, xd);
            xd = dup2(xc.z);
            fma2(acc[0][6], w01.x, xd); fma2(acc[1][6], w01.y, xd);
            fma2(acc[2][6], w23.x, xd); fma2(acc[3][6], w23.y, xd);
            xd = dup2(xc.w);
            fma2(acc[0][7], w01.x, xd); fma2(acc[1][7], w01.y, xd);
            fma2(acc[2][7], w23.x, xd); fma2(acc[3][7], w23.y, xd);
        }

        if (has_next) {
            int pn = p ^ 1;
            #pragma unroll
            for (int i = 0; i < 4; i++) {
                int r = r0 + i * 128;
                Ws[pn][wkv*4+0][r] = wst[i].x;
                Ws[pn][wkv*4+1][r] = wst[i].y;
                Ws[pn][wkv*4+2][r] = wst[i].z;
                Ws[pn][wkv*4+3][r] = wst[i].w;
            }
            if (t < 64) {
                Xs[pn][xkv*4+0][xb] = xst.x;
                Xs[pn][xkv*4+1][xb] = xst.y;
                Xs[pn][xkv*4+2][xb] = xst.z;
                Xs[pn][xkv*4+3][xb] = xst.w;
            }
        }
        __syncthreads();
        p ^= 1;
    }

    float* pp = part + (size_t)blockIdx.y * BSZ * M;
    #pragma unroll
    for (int bj = 0; bj < 8; bj++) {
        int b = tx * 8 + bj;
        float* dst = pp + (size_t)b * M + m0 + ty * 8;
        ulonglong2 lo = make_ulonglong2(acc[0][bj], acc[1][bj]);
        ulonglong2 hi = make_ulonglong2(acc[2][bj], acc[3][bj]);
        *reinterpret_cast<ulonglong2*>(dst)     = lo;
        *reinterpret_cast<ulonglong2*>(dst + 4) = hi;
    }
}

// ---------------------------------------------------------------
// reduce partials (unchanged)
// ---------------------------------------------------------------
__global__ void __launch_bounds__(256)
reduce_part_kernel(const float4* __restrict__ part, const float4* __restrict__ bias,
                   float4* __restrict__ out, int M4, int nsplit)
{
    int idx = blockIdx.x * 256 + threadIdx.x;
    if (idx >= BSZ * M4) return;
    const size_t step = (size_t)BSZ * M4;
    float4 a0 = bias ? bias[idx % M4] : make_float4(0.f, 0.f, 0.f, 0.f);
    float4 a1 = make_float4(0.f, 0.f, 0.f, 0.f);
    float4 a2 = a1, a3 = a1;
    int s = 0;
    for (; s + 4 <= nsplit; s += 4) {
        float4 p0 = part[(size_t)(s+0) * step + idx];
        float4 p1 = part[(size_t)(s+1) * step + idx];
        float4 p2 = part[(size_t)(s+2) * step + idx];
        float4 p3 = part[(size_t)(s+3) * step + idx];
        a0.x += p0.x; a0.y += p0.y; a0.z += p0.z; a0.w += p0.w;
        a1.x += p1.x; a1.y += p1.y; a1.z += p1.z; a1.w += p1.w;
        a2.x += p2.x; a2.y += p2.y; a2.z += p2.z; a2.w += p2.w;
        a3.x += p3.x; a3.y += p3.y; a3.z += p3.z; a3.w += p3.w;
    }
    for (; s < nsplit; s++) {
        float4 pv = part[(size_t)s * step + idx];
        a0.x += pv.x; a0.y += pv.y; a0.z += pv.z; a0.w += pv.w;
    }
    a0.x += a1.x + a2.x + a3.x;
    a0.y += a1.y + a2.y + a3.y;
    a0.z += a1.z + a2.z + a3.z;
    a0.w += a1.w + a2.w + a3.w;
    out[idx] = a0;
}

// ---------------------------------------------------------------
// Flash-decode partial v5: R6 structure, 2 heads per block (GROUP split),
// grid (NCHUNK*2, NUM_KV, BSZ), 128 threads (4 warps), higher occupancy.
// Twin blocks (same chunk, different head pair) are grid-adjacent -> the
// second KV read hits L2.
// ---------------------------------------------------------------
__global__ void __launch_bounds__(128, 5)
attn_partial_kernel(const float* __restrict__ kvc,
                    const int*   __restrict__ seq_lens,
                    const int*   __restrict__ slot_map)
{
    int b      = blockIdx.z;
    int kvh    = blockIdx.y;
    int c      = blockIdx.x >> 1;
    int gsplit = blockIdx.x & 1;          // head pair: gsplit*2 .. gsplit*2+1

    int seq   = seq_lens[b];
    int start = c * CHUNK;
    if (start >= seq) return;
    int end  = min(seq, start + CHUNK);
    int slot = slot_map[b];

    int lane = threadIdx.x & 31;
    int warp = threadIdx.x >> 5;   // 0..3

    float qr[G2][4];
    #pragma unroll
    for (int g = 0; g < G2; g++) {
        float4 q4 = *reinterpret_cast<const float4*>(
            &g_qkv[b * QKV_OUT + (kvh * GROUP + gsplit * G2 + g) * HEAD_DIM + lane * 4]);
        qr[g][0] = q4.x * QSCALE; qr[g][1] = q4.y * QSCALE;
        qr[g][2] = q4.z * QSCALE; qr[g][3] = q4.w * QSCALE;
    }

    float m[G2], l[G2], o[G2][4];
    #pragma unroll
    for (int g = 0; g < G2; g++) {
        m[g] = -CUDART_INF_F; l[g] = 0.f;
        o[g][0] = o[g][1] = o[g][2] = o[g][3] = 0.f;
    }

    const size_t VPLANE = (size_t)BSZ * MAX_SEQ * NUM_KV * HEAD_DIM;
    const float* knew = &g_qkv[b * QKV_OUT + NUM_HEADS * HEAD_DIM            + kvh * HEAD_DIM];
    const float* vnew = &g_qkv[b * QKV_OUT + (NUM_HEADS + NUM_KV) * HEAD_DIM + kvh * HEAD_DIM];

    auto ldkv = [&](int s, float4& kk, float4& vv) {
        size_t base = (((size_t)b * MAX_SEQ + s) * NUM_KV + kvh) * HEAD_DIM + lane * 4;
        if (s == slot) {
            kk = *reinterpret_cast<const float4*>(knew + lane * 4);
            vv = *reinterpret_cast<const float4*>(vnew + lane * 4);
        } else {
            kk = *reinterpret_cast<const float4*>(&kvc[base]);
            vv = *reinterpret_cast<const float4*>(&kvc[VPLANE + base]);
        }
    };

    int s = start + warp * 4;
    if (s < end) {
        float4 kc[4], vc[4];
        #pragma unroll
        for (int j = 0; j < 4; j++) { kc[j] = make_float4(0,0,0,0); vc[j] = kc[j]; }
        #pragma unroll
        for (int j = 0; j < 4; j++)
            if (s + j < end) ldkv(s + j, kc[j], vc[j]);

        for (;;) {
            int sn = s + 16;
            bool more = (sn < end);
            float4 kn[4], vn[4];
            if (more) {
                #pragma unroll
                for (int j = 0; j < 4; j++)
                    if (sn + j < end) ldkv(sn + j, kn[j], vn[j]);
            }

            float sc[4][G2];
            #pragma unroll
            for (int j = 0; j < 4; j++) {
                #pragma unroll
                for (int g = 0; g < G2; g++)
                    sc[j][g] = qr[g][0]*kc[j].x + qr[g][1]*kc[j].y
                             + qr[g][2]*kc[j].z + qr[g][3]*kc[j].w;
            }
            #pragma unroll
            for (int off = 16; off >= 1; off >>= 1) {
                #pragma unroll
                for (int j = 0; j < 4; j++)
                    #pragma unroll
                    for (int g = 0; g < G2; g++)
                        sc[j][g] += __shfl_xor_sync(0xffffffffu, sc[j][g], off);
            }
            #pragma unroll
            for (int j = 1; j < 4; j++) {
                if (s + j >= end) {
                    #pragma unroll
                    for (int g = 0; g < G2; g++) sc[j][g] = -CUDART_INF_F;
                }
            }

            #pragma unroll
            for (int g = 0; g < G2; g++) {
                float mx = fmaxf(fmaxf(sc[0][g], sc[1][g]), fmaxf(sc[2][g], sc[3][g]));
                float p0, p1, p2, p3;
                if (mx <= m[g]) {
                    p0 = exp2f(sc[0][g] - m[g]); p1 = exp2f(sc[1][g] - m[g]);
                    p2 = exp2f(sc[2][g] - m[g]); p3 = exp2f(sc[3][g] - m[g]);
                    l[g] += (p0 + p1) + (p2 + p3);
                } else {
                    float corr = exp2f(m[g] - mx);
                    m[g] = mx;
                    p0 = exp2f(sc[0][g] - mx); p1 = exp2f(sc[1][g] - mx);
                    p2 = exp2f(sc[2][g] - mx); p3 = exp2f(sc[3][g] - mx);
                    l[g] = l[g] * corr + (p0 + p1) + (p2 + p3);
                    o[g][0] *= corr; o[g][1] *= corr; o[g][2] *= corr; o[g][3] *= corr;
                }
                o[g][0] += p0*vc[0].x + p1*vc[1].x + p2*vc[2].x + p3*vc[3].x;
                o[g][1] += p0*vc[0].y + p1*vc[1].y + p2*vc[2].y + p3*vc[3].y;
                o[g][2] += p0*vc[0].z + p1*vc[1].z + p2*vc[2].z + p3*vc[3].z;
                o[g][3] += p0*vc[0].w + p1*vc[1].w + p2*vc[2].w + p3*vc[3].w;
            }

            if (!more) break;
            #pragma unroll
            for (int j = 0; j < 4; j++) { kc[j] = kn[j]; vc[j] = vn[j]; }
            s = sn;
        }
    }

    // ---- cross-warp merge (4 warps, 2 heads) ----
    __shared__ float sm_m[4][G2];
    __shared__ float sm_l[4][G2];
    __shared__ float sm_o[4][G2][HEAD_DIM];

    if (lane == 0) {
        #pragma unroll
        for (int g = 0; g < G2; g++) { sm_m[warp][g] = m[g]; sm_l[warp][g] = l[g]; }
    }
    #pragma unroll
    for (int g = 0; g < G2; g++) {
        sm_o[warp][g][lane*4+0] = o[g][0];
        sm_o[warp][g][lane*4+1] = o[g][1];
        sm_o[warp][g][lane*4+2] = o[g][2];
        sm_o[warp][g][lane*4+3] = o[g][3];
    }
    __syncthreads();

    if (warp < G2) {
        int g = warp;
        int gq = gsplit * G2 + g;
        float M = -CUDART_INF_F;
        #pragma unroll
        for (int w = 0; w < 4; w++) M = fmaxf(M, sm_m[w][g]);
        float L = 0.f, O0 = 0.f, O1 = 0.f, O2 = 0.f, O3 = 0.f;
        #pragma unroll
        for (int w = 0; w < 4; w++) {
            float e = exp2f(sm_m[w][g] - M);
            L  += sm_l[w][g] * e;
            O0 += sm_o[w][g][lane*4+0] * e;
            O1 += sm_o[w][g][lane*4+1] * e;
            O2 += sm_o[w][g][lane*4+2] * e;
            O3 += sm_o[w][g][lane*4+3] * e;
        }
        size_t pidx = (((size_t)b * NUM_KV + kvh) * GROUP + gq) * NCHUNK + c;
        *reinterpret_cast<float4*>(&g_po[pidx * HEAD_DIM + lane * 4]) =
            make_float4(O0, O1, O2, O3);
        if (lane == 0) { g_pml[pidx*2] = M; g_pml[pidx*2+1] = L; }
    }
}

// ---------------------------------------------------------------
// Chunk merge (unchanged from R6)
// ---------------------------------------------------------------
__global__ void __launch_bounds__(128)
attn_reduce_kernel(const int* __restrict__ seq_lens)
{
    int h = blockIdx.x;
    int b = blockIdx.y;
    int d = threadIdx.x;
    int lane = d & 31, warp = d >> 5;
    int seq = seq_lens[b];
    int nch = (seq + CHUNK - 1) / CHUNK;
    int kvh = h >> 2, g = h & 3;

    size_t base = (((size_t)b * NUM_KV + kvh) * GROUP + g) * NCHUNK;

    __shared__ float es[NCHUNK];
    __shared__ float Ls;

    if (warp == 0) {
        float mm = -CUDART_INF_F, ll = 0.f;
        if (lane < nch) {
            float2 ml = *reinterpret_cast<const float2*>(&g_pml[(base + lane) * 2]);
            mm = ml.x; ll = ml.y;
        }
        float M = mm;
        #pragma unroll
        for (int off = 16; off >= 1; off >>= 1)
            M = fmaxf(M, __shfl_xor_sync(0xffffffffu, M, off));
        float e = (lane < nch) ? exp2f(mm - M) : 0.f;
        float le = ll * e;
        #pragma unroll
        for (int off = 16; off >= 1; off >>= 1)
            le += __shfl_xor_sync(0xffffffffu, le, off);
        es[lane] = e;
        if (lane == 0) Ls = le;
    }
    __syncthreads();

    float O0 = 0.f, O1 = 0.f, O2 = 0.f, O3 = 0.f;
    int cc = 0;
    for (; cc + 4 <= nch; cc += 4) {
        O0 += g_po[(base + cc + 0) * HEAD_DIM + d] * es[cc + 0];
        O1 += g_po[(base + cc + 1) * HEAD_DIM + d] * es[cc + 1];
        O2 += g_po[(base + cc + 2) * HEAD_DIM + d] * es[cc + 2];
        O3 += g_po[(base + cc + 3) * HEAD_DIM + d] * es[cc + 3];
    }
    for (; cc < nch; cc++)
        O0 += g_po[(base + cc) * HEAD_DIM + d] * es[cc];

    g_attn[(size_t)b * HIDDEN + h * HEAD_DIM + d] = ((O0 + O1) + (O2 + O3)) / Ls;
}

// ---------------------------------------------------------------
extern "C" void kernel_launch(void* const* d_in, const int* in_sizes, int n_in,
                              void* d_out, int out_size)
{
    const float* hidden = (const float*)d_in[0];
    const float* kvc    = (const float*)d_in[2];
    const int*   slot   = (const int*)  d_in[3];
    const int*   seql   = (const int*)  d_in[4];
    const float* Wqkv   = (const float*)d_in[5];
    const float* bqkv   = (const float*)d_in[6];
    const float* Wo     = (const float*)d_in[7];
    float*       out    = (float*)d_out;

    void *pq = nullptr, *pa = nullptr, *pp = nullptr;
    cudaGetSymbolAddress(&pq, g_qkv);
    cudaGetSymbolAddress(&pa, g_attn);
    cudaGetSymbolAddress(&pp, g_part);
    float* qkv  = (float*)pq;
    float* attn = (float*)pa;
    float* part = (float*)pp;

    // 1) QKV projection: partials + reduce (bias folded into reduce)
    gemm8x8_kernel<<<dim3(QKV_OUT / GBM, QKV_SPLIT), 256>>>(Wqkv, hidden, part, QKV_OUT, HIDDEN, QKV_SPLIT);
    reduce_part_kernel<<<(BSZ * QKV_OUT / 4 + 255) / 256, 256>>>(
        (const float4*)part, (const float4*)bqkv, (float4*)qkv, QKV_OUT / 4, QKV_SPLIT);

    // 2) flash-decode partials (2 heads/block, twin blocks share KV via L2)
    attn_partial_kernel<<<dim3(NCHUNK * 2, NUM_KV, BSZ), 128>>>(kvc, seql, slot);

    // 3) merge partials
    attn_reduce_kernel<<<dim3(NUM_HEADS, BSZ), 128>>>(seql);

    // 4) output projection: partials + reduce (writes d_out directly)
    gemm8x8_kernel<<<dim3(HIDDEN / GBM, WO_SPLIT), 256>>>(Wo, attn, part, HIDDEN, HIDDEN, WO_SPLIT);
    reduce_part_kernel<<<(BSZ * HIDDEN / 4 + 255) / 256, 256>>>(
        (const float4*)part, nullptr, (float4*)out, HIDDEN / 4, WO_SPLIT);
}

// round 12
// speedup vs baseline: 1.4172x; 1.4172x over previous
#include <cuda_runtime.h>
#include <math_constants.h>

#define NUM_HEADS 32
#define NUM_KV    8
#define HEAD_DIM  128
#define HIDDEN    4096
#define BSZ       32
#define MAX_SEQ   4096
#define GROUP     4
#define QKV_OUT   6144
#define CHUNK     128
#define NCHUNK    32
// attention scale * log2(e): softmax in exp2 domain
#define QSCALE    (0.08838834764831845f * 1.4426950408889634f)

// GEMM tiling: BM=512, BK=8, 128 threads, per-thread 16m x 8b
#define GBM 512
#define GBK 8
#define WST 516
#define XST 36
#define QKV_SPLIT 24     // 12 m-blocks x 24 = 288 blocks
#define WO_SPLIT  36     // 8 m-blocks x 36 = 288 blocks

// ---------------- scratch (no allocs allowed) ----------------
__device__ float g_qkv [BSZ * QKV_OUT];
__device__ float g_attn[BSZ * NUM_HEADS * HEAD_DIM];
__device__ float g_part[QKV_SPLIT * BSZ * QKV_OUT];
__device__ float g_po  [BSZ * NUM_KV * GROUP * NCHUNK * HEAD_DIM];
__device__ float g_pml [BSZ * NUM_KV * GROUP * NCHUNK * 2];

// packed fp32x2 ops (Blackwell)
__device__ __forceinline__ void fma2(unsigned long long& d,
                                     unsigned long long a,
                                     unsigned long long b) {
    asm("fma.rn.f32x2 %0, %1, %2, %0;" : "+l"(d) : "l"(a), "l"(b));
}
__device__ __forceinline__ unsigned long long dup2(float v) {
    unsigned long long r;
    asm("mov.b64 %0, {%1, %1};" : "=l"(r) : "f"(v));
    return r;
}

// ---------------------------------------------------------------
// Split-K GEMM, 16m x 8b register tiles (0.75 B/MAC smem traffic).
// 128 threads, BM=512, BK=8, double-buffered, partials to scratch.
// ---------------------------------------------------------------
__global__ void __launch_bounds__(128, 2)
gemm16x8_kernel(const float* __restrict__ W, const float* __restrict__ x,
                float* __restrict__ part, int M, int K, int nsplit)
{
    __shared__ __align__(16) float Ws[2][GBK][WST];
    __shared__ __align__(16) float Xs[2][GBK][XST];

    const int m0    = blockIdx.x * GBM;
    const int tot   = K / GBK;
    const int tile0 = (blockIdx.y * tot) / nsplit;
    const int tile1 = ((blockIdx.y + 1) * tot) / nsplit;

    const int t   = threadIdx.x;      // 0..127
    const int ty  = t >> 2;           // 0..31 -> rows m0 + ty*16 .. +15
    const int tx  = t & 3;            // batches tx*8 .. +7
    const int r0  = t >> 1;           // W load base row (0..63), +64 per i
    const int wkv = t & 1;            // which float4 of the 8-k chunk
    const int xb  = t & 31;           // x load batch (t<64)
    const int xkv = t >> 5;           // 0..1 (t<64)

    float4 wst[8];
    float4 xst;

    // ---- prologue: load tile0 ----
    {
        const float* wp = W + (size_t)(m0 + r0) * K + (size_t)tile0 * GBK + wkv * 4;
        #pragma unroll
        for (int i = 0; i < 8; i++)
            wst[i] = *reinterpret_cast<const float4*>(wp + (size_t)i * 64 * K);
        if (t < 64)
            xst = *reinterpret_cast<const float4*>(x + (size_t)xb * K + (size_t)tile0 * GBK + xkv * 4);

        #pragma unroll
        for (int i = 0; i < 8; i++) {
            int r = r0 + i * 64;
            Ws[0][wkv*4+0][r] = wst[i].x;
            Ws[0][wkv*4+1][r] = wst[i].y;
            Ws[0][wkv*4+2][r] = wst[i].z;
            Ws[0][wkv*4+3][r] = wst[i].w;
        }
        if (t < 64) {
            Xs[0][xkv*4+0][xb] = xst.x;
            Xs[0][xkv*4+1][xb] = xst.y;
            Xs[0][xkv*4+2][xb] = xst.z;
            Xs[0][xkv*4+3][xb] = xst.w;
        }
    }
    __syncthreads();

    unsigned long long acc[8][8];
    #pragma unroll
    for (int i = 0; i < 8; i++)
        #pragma unroll
        for (int j = 0; j < 8; j++) acc[i][j] = 0ull;

    int p = 0;
    for (int tile = tile0; tile < tile1; tile++) {
        const bool has_next = (tile + 1 < tile1);
        if (has_next) {
            const float* wp = W + (size_t)(m0 + r0) * K + (size_t)(tile + 1) * GBK + wkv * 4;
            #pragma unroll
            for (int i = 0; i < 8; i++)
                wst[i] = *reinterpret_cast<const float4*>(wp + (size_t)i * 64 * K);
            if (t < 64)
                xst = *reinterpret_cast<const float4*>(x + (size_t)xb * K + (size_t)(tile + 1) * GBK + xkv * 4);
        }

        #pragma unroll
        for (int k = 0; k < GBK; k++) {
            ulonglong2 wq0 = *reinterpret_cast<const ulonglong2*>(&Ws[p][k][ty * 16]);
            ulonglong2 wq1 = *reinterpret_cast<const ulonglong2*>(&Ws[p][k][ty * 16 + 4]);
            ulonglong2 wq2 = *reinterpret_cast<const ulonglong2*>(&Ws[p][k][ty * 16 + 8]);
            ulonglong2 wq3 = *reinterpret_cast<const ulonglong2*>(&Ws[p][k][ty * 16 + 12]);
            float4 xa = *reinterpret_cast<const float4*>(&Xs[p][k][tx * 8]);
            float4 xc = *reinterpret_cast<const float4*>(&Xs[p][k][tx * 8 + 4]);
            float xs8[8] = {xa.x, xa.y, xa.z, xa.w, xc.x, xc.y, xc.z, xc.w};
            #pragma unroll
            for (int bj = 0; bj < 8; bj++) {
                unsigned long long xd = dup2(xs8[bj]);
                fma2(acc[0][bj], wq0.x, xd); fma2(acc[1][bj], wq0.y, xd);
                fma2(acc[2][bj], wq1.x, xd); fma2(acc[3][bj], wq1.y, xd);
                fma2(acc[4][bj], wq2.x, xd); fma2(acc[5][bj], wq2.y, xd);
                fma2(acc[6][bj], wq3.x, xd); fma2(acc[7][bj], wq3.y, xd);
            }
        }

        if (has_next) {
            int pn = p ^ 1;
            #pragma unroll
            for (int i = 0; i < 8; i++) {
                int r = r0 + i * 64;
                Ws[pn][wkv*4+0][r] = wst[i].x;
                Ws[pn][wkv*4+1][r] = wst[i].y;
                Ws[pn][wkv*4+2][r] = wst[i].z;
                Ws[pn][wkv*4+3][r] = wst[i].w;
            }
            if (t < 64) {
                Xs[pn][xkv*4+0][xb] = xst.x;
                Xs[pn][xkv*4+1][xb] = xst.y;
                Xs[pn][xkv*4+2][xb] = xst.z;
                Xs[pn][xkv*4+3][xb] = xst.w;
            }
        }
        __syncthreads();
        p ^= 1;
    }

    // ---- epilogue: plain vector stores of partials (16 m floats / batch) ----
    float* pp = part + (size_t)blockIdx.y * BSZ * M;
    #pragma unroll
    for (int bj = 0; bj < 8; bj++) {
        int b = tx * 8 + bj;
        float* dst = pp + (size_t)b * M + m0 + ty * 16;
        *reinterpret_cast<ulonglong2*>(dst)      = make_ulonglong2(acc[0][bj], acc[1][bj]);
        *reinterpret_cast<ulonglong2*>(dst + 4)  = make_ulonglong2(acc[2][bj], acc[3][bj]);
        *reinterpret_cast<ulonglong2*>(dst + 8)  = make_ulonglong2(acc[4][bj], acc[5][bj]);
        *reinterpret_cast<ulonglong2*>(dst + 12) = make_ulonglong2(acc[6][bj], acc[7][bj]);
    }
}

// ---------------------------------------------------------------
// reduce partials (unchanged)
// ---------------------------------------------------------------
__global__ void __launch_bounds__(256)
reduce_part_kernel(const float4* __restrict__ part, const float4* __restrict__ bias,
                   float4* __restrict__ out, int M4, int nsplit)
{
    int idx = blockIdx.x * 256 + threadIdx.x;
    if (idx >= BSZ * M4) return;
    const size_t step = (size_t)BSZ * M4;
    float4 a0 = bias ? bias[idx % M4] : make_float4(0.f, 0.f, 0.f, 0.f);
    float4 a1 = make_float4(0.f, 0.f, 0.f, 0.f);
    float4 a2 = a1, a3 = a1;
    int s = 0;
    for (; s + 4 <= nsplit; s += 4) {
        float4 p0 = part[(size_t)(s+0) * step + idx];
        float4 p1 = part[(size_t)(s+1) * step + idx];
        float4 p2 = part[(size_t)(s+2) * step + idx];
        float4 p3 = part[(size_t)(s+3) * step + idx];
        a0.x += p0.x; a0.y += p0.y; a0.z += p0.z; a0.w += p0.w;
        a1.x += p1.x; a1.y += p1.y; a1.z += p1.z; a1.w += p1.w;
        a2.x += p2.x; a2.y += p2.y; a2.z += p2.z; a2.w += p2.w;
        a3.x += p3.x; a3.y += p3.y; a3.z += p3.z; a3.w += p3.w;
    }
    for (; s < nsplit; s++) {
        float4 pv = part[(size_t)s * step + idx];
        a0.x += pv.x; a0.y += pv.y; a0.z += pv.z; a0.w += pv.w;
    }
    a0.x += a1.x + a2.x + a3.x;
    a0.y += a1.y + a2.y + a3.y;
    a0.z += a1.z + a2.z + a3.z;
    a0.w += a1.w + a2.w + a3.w;
    out[idx] = a0;
}

// ---------------------------------------------------------------
// Flash-decode partial: EXACT R6 measured-best version.
// grid (NCHUNK, NUM_KV, BSZ), 128 threads (4 warps).
// ---------------------------------------------------------------
__global__ void __launch_bounds__(128, 4)
attn_partial_kernel(const float* __restrict__ kvc,
                    const int*   __restrict__ seq_lens,
                    const int*   __restrict__ slot_map)
{
    int b   = blockIdx.z;
    int kvh = blockIdx.y;
    int c   = blockIdx.x;

    int seq   = seq_lens[b];
    int start = c * CHUNK;
    if (start >= seq) return;
    int end  = min(seq, start + CHUNK);
    int slot = slot_map[b];

    int lane = threadIdx.x & 31;
    int warp = threadIdx.x >> 5;   // 0..3

    float qr[GROUP][4];
    #pragma unroll
    for (int g = 0; g < GROUP; g++) {
        float4 q4 = *reinterpret_cast<const float4*>(
            &g_qkv[b * QKV_OUT + (kvh * GROUP + g) * HEAD_DIM + lane * 4]);
        qr[g][0] = q4.x * QSCALE; qr[g][1] = q4.y * QSCALE;
        qr[g][2] = q4.z * QSCALE; qr[g][3] = q4.w * QSCALE;
    }

    float m[GROUP], l[GROUP], o[GROUP][4];
    #pragma unroll
    for (int g = 0; g < GROUP; g++) {
        m[g] = -CUDART_INF_F; l[g] = 0.f;
        o[g][0] = o[g][1] = o[g][2] = o[g][3] = 0.f;
    }

    const size_t VPLANE = (size_t)BSZ * MAX_SEQ * NUM_KV * HEAD_DIM;
    const float* knew = &g_qkv[b * QKV_OUT + NUM_HEADS * HEAD_DIM            + kvh * HEAD_DIM];
    const float* vnew = &g_qkv[b * QKV_OUT + (NUM_HEADS + NUM_KV) * HEAD_DIM + kvh * HEAD_DIM];

    auto ldkv = [&](int s, float4& kk, float4& vv) {
        size_t base = (((size_t)b * MAX_SEQ + s) * NUM_KV + kvh) * HEAD_DIM + lane * 4;
        if (s == slot) {
            kk = *reinterpret_cast<const float4*>(knew + lane * 4);
            vv = *reinterpret_cast<const float4*>(vnew + lane * 4);
        } else {
            kk = *reinterpret_cast<const float4*>(&kvc[base]);
            vv = *reinterpret_cast<const float4*>(&kvc[VPLANE + base]);
        }
    };

    int s = start + warp * 4;
    if (s < end) {
        float4 kc[4], vc[4];
        #pragma unroll
        for (int j = 0; j < 4; j++) { kc[j] = make_float4(0,0,0,0); vc[j] = kc[j]; }
        #pragma unroll
        for (int j = 0; j < 4; j++)
            if (s + j < end) ldkv(s + j, kc[j], vc[j]);

        for (;;) {
            int sn = s + 16;
            bool more = (sn < end);
            float4 kn[4], vn[4];
            if (more) {
                #pragma unroll
                for (int j = 0; j < 4; j++)
                    if (sn + j < end) ldkv(sn + j, kn[j], vn[j]);
            }

            float sc[4][GROUP];
            #pragma unroll
            for (int j = 0; j < 4; j++) {
                #pragma unroll
                for (int g = 0; g < GROUP; g++)
                    sc[j][g] = qr[g][0]*kc[j].x + qr[g][1]*kc[j].y
                             + qr[g][2]*kc[j].z + qr[g][3]*kc[j].w;
            }
            #pragma unroll
            for (int off = 16; off >= 1; off >>= 1) {
                #pragma unroll
                for (int j = 0; j < 4; j++)
                    #pragma unroll
                    for (int g = 0; g < GROUP; g++)
                        sc[j][g] += __shfl_xor_sync(0xffffffffu, sc[j][g], off);
            }
            #pragma unroll
            for (int j = 1; j < 4; j++) {
                if (s + j >= end) {
                    #pragma unroll
                    for (int g = 0; g < GROUP; g++) sc[j][g] = -CUDART_INF_F;
                }
            }

            #pragma unroll
            for (int g = 0; g < GROUP; g++) {
                float mx = fmaxf(fmaxf(sc[0][g], sc[1][g]), fmaxf(sc[2][g], sc[3][g]));
                float p0, p1, p2, p3;
                if (mx <= m[g]) {
                    p0 = exp2f(sc[0][g] - m[g]); p1 = exp2f(sc[1][g] - m[g]);
                    p2 = exp2f(sc[2][g] - m[g]); p3 = exp2f(sc[3][g] - m[g]);
                    l[g] += (p0 + p1) + (p2 + p3);
                } else {
                    float corr = exp2f(m[g] - mx);
                    m[g] = mx;
                    p0 = exp2f(sc[0][g] - mx); p1 = exp2f(sc[1][g] - mx);
                    p2 = exp2f(sc[2][g] - mx); p3 = exp2f(sc[3][g] - mx);
                    l[g] = l[g] * corr + (p0 + p1) + (p2 + p3);
                    o[g][0] *= corr; o[g][1] *= corr; o[g][2] *= corr; o[g][3] *= corr;
                }
                o[g][0] += p0*vc[0].x + p1*vc[1].x + p2*vc[2].x + p3*vc[3].x;
                o[g][1] += p0*vc[0].y + p1*vc[1].y + p2*vc[2].y + p3*vc[3].y;
                o[g][2] += p0*vc[0].z + p1*vc[1].z + p2*vc[2].z + p3*vc[3].z;
                o[g][3] += p0*vc[0].w + p1*vc[1].w + p2*vc[2].w + p3*vc[3].w;
            }

            if (!more) break;
            #pragma unroll
            for (int j = 0; j < 4; j++) { kc[j] = kn[j]; vc[j] = vn[j]; }
            s = sn;
        }
    }

    __shared__ float sm_m[4][GROUP];
    __shared__ float sm_l[4][GROUP];
    __shared__ float sm_o[4][GROUP][HEAD_DIM];

    if (lane == 0) {
        #pragma unroll
        for (int g = 0; g < GROUP; g++) { sm_m[warp][g] = m[g]; sm_l[warp][g] = l[g]; }
    }
    #pragma unroll
    for (int g = 0; g < GROUP; g++) {
        sm_o[warp][g][lane*4+0] = o[g][0];
        sm_o[warp][g][lane*4+1] = o[g][1];
        sm_o[warp][g][lane*4+2] = o[g][2];
        sm_o[warp][g][lane*4+3] = o[g][3];
    }
    __syncthreads();

    {
        int g = warp;
        float M = -CUDART_INF_F;
        #pragma unroll
        for (int w = 0; w < 4; w++) M = fmaxf(M, sm_m[w][g]);
        float L = 0.f, O0 = 0.f, O1 = 0.f, O2 = 0.f, O3 = 0.f;
        #pragma unroll
        for (int w = 0; w < 4; w++) {
            float e = exp2f(sm_m[w][g] - M);
            L  += sm_l[w][g] * e;
            O0 += sm_o[w][g][lane*4+0] * e;
            O1 += sm_o[w][g][lane*4+1] * e;
            O2 += sm_o[w][g][lane*4+2] * e;
            O3 += sm_o[w][g][lane*4+3] * e;
        }
        size_t pidx = (((size_t)b * NUM_KV + kvh) * GROUP + g) * NCHUNK + c;
        *reinterpret_cast<float4*>(&g_po[pidx * HEAD_DIM + lane * 4]) =
            make_float4(O0, O1, O2, O3);
        if (lane == 0) { g_pml[pidx*2] = M; g_pml[pidx*2+1] = L; }
    }
}

// ---------------------------------------------------------------
// Chunk merge (unchanged)
// ---------------------------------------------------------------
__global__ void __launch_bounds__(128)
attn_reduce_kernel(const int* __restrict__ seq_lens)
{
    int h = blockIdx.x;
    int b = blockIdx.y;
    int d = threadIdx.x;
    int lane = d & 31, warp = d >> 5;
    int seq = seq_lens[b];
    int nch = (seq + CHUNK - 1) / CHUNK;
    int kvh = h >> 2, g = h & 3;

    size_t base = (((size_t)b * NUM_KV + kvh) * GROUP + g) * NCHUNK;

    __shared__ float es[NCHUNK];
    __shared__ float Ls;

    if (warp == 0) {
        float mm = -CUDART_INF_F, ll = 0.f;
        if (lane < nch) {
            float2 ml = *reinterpret_cast<const float2*>(&g_pml[(base + lane) * 2]);
            mm = ml.x; ll = ml.y;
        }
        float M = mm;
        #pragma unroll
        for (int off = 16; off >= 1; off >>= 1)
            M = fmaxf(M, __shfl_xor_sync(0xffffffffu, M, off));
        float e = (lane < nch) ? exp2f(mm - M) : 0.f;
        float le = ll * e;
        #pragma unroll
        for (int off = 16; off >= 1; off >>= 1)
            le += __shfl_xor_sync(0xffffffffu, le, off);
        es[lane] = e;
        if (lane == 0) Ls = le;
    }
    __syncthreads();

    float O0 = 0.f, O1 = 0.f, O2 = 0.f, O3 = 0.f;
    int cc = 0;
    for (; cc + 4 <= nch; cc += 4) {
        O0 += g_po[(base + cc + 0) * HEAD_DIM + d] * es[cc + 0];
        O1 += g_po[(base + cc + 1) * HEAD_DIM + d] * es[cc + 1];
        O2 += g_po[(base + cc + 2) * HEAD_DIM + d] * es[cc + 2];
        O3 += g_po[(base + cc + 3) * HEAD_DIM + d] * es[cc + 3];
    }
    for (; cc < nch; cc++)
        O0 += g_po[(base + cc) * HEAD_DIM + d] * es[cc];

    g_attn[(size_t)b * HIDDEN + h * HEAD_DIM + d] = ((O0 + O1) + (O2 + O3)) / Ls;
}

// ---------------------------------------------------------------
extern "C" void kernel_launch(void* const* d_in, const int* in_sizes, int n_in,
                              void* d_out, int out_size)
{
    const float* hidden = (const float*)d_in[0];
    const float* kvc    = (const float*)d_in[2];
    const int*   slot   = (const int*)  d_in[3];
    const int*   seql   = (const int*)  d_in[4];
    const float* Wqkv   = (const float*)d_in[5];
    const float* bqkv   = (const float*)d_in[6];
    const float* Wo     = (const float*)d_in[7];
    float*       out    = (float*)d_out;

    void *pq = nullptr, *pa = nullptr, *pp = nullptr;
    cudaGetSymbolAddress(&pq, g_qkv);
    cudaGetSymbolAddress(&pa, g_attn);
    cudaGetSymbolAddress(&pp, g_part);
    float* qkv  = (float*)pq;
    float* attn = (float*)pa;
    float* part = (float*)pp;

    // 1) QKV projection: partials + reduce (bias folded into reduce)
    gemm16x8_kernel<<<dim3(QKV_OUT / GBM, QKV_SPLIT), 128>>>(Wqkv, hidden, part, QKV_OUT, HIDDEN, QKV_SPLIT);
    reduce_part_kernel<<<(BSZ * QKV_OUT / 4 + 255) / 256, 256>>>(
        (const float4*)part, (const float4*)bqkv, (float4*)qkv, QKV_OUT / 4, QKV_SPLIT);

    // 2) flash-decode partials (R6 measured-best)
    attn_partial_kernel<<<dim3(NCHUNK, NUM_KV, BSZ), 128>>>(kvc, seql, slot);

    // 3) merge partials
    attn_reduce_kernel<<<dim3(NUM_HEADS, BSZ), 128>>>(seql);

    // 4) output projection: partials + reduce (writes d_out directly)
    gemm16x8_kernel<<<dim3(HIDDEN / GBM, WO_SPLIT), 128>>>(Wo, attn, part, HIDDEN, HIDDEN, WO_SPLIT);
    reduce_part_kernel<<<(BSZ * HIDDEN / 4 + 255) / 256, 256>>>(
        (const float4*)part, nullptr, (float4*)out, HIDDEN / 4, WO_SPLIT);
}

// round 13
// speedup vs baseline: 1.4587x; 1.0293x over previous
#include <cuda_runtime.h>
#include <math_constants.h>

#define NUM_HEADS 32
#define NUM_KV    8
#define HEAD_DIM  128
#define HIDDEN    4096
#define BSZ       32
#define MAX_SEQ   4096
#define GROUP     4
#define QKV_OUT   6144
#define CHUNK     128
#define NCHUNK    32
// attention scale * log2(e): softmax in exp2 domain
#define QSCALE    (0.08838834764831845f * 1.4426950408889634f)

// GEMM tiling: BM=256, BK=8, 128 threads, per-thread 8m x 8b, 4 blocks/SM
#define GBM 256
#define GBK 8
#define WST 260
#define XST 36
#define QKV_SPLIT 12     // 24 m-blocks x 12 = 288 blocks
#define WO_SPLIT  18     // 16 m-blocks x 18 = 288 blocks

// ---------------- scratch (no allocs allowed) ----------------
__device__ float g_qkv [BSZ * QKV_OUT];
__device__ float g_attn[BSZ * NUM_HEADS * HEAD_DIM];
__device__ float g_part[QKV_SPLIT * BSZ * QKV_OUT];   // 9.4 MB (= WO_SPLIT*BSZ*HIDDEN)
__device__ float g_po  [BSZ * NUM_KV * GROUP * NCHUNK * HEAD_DIM];
__device__ float g_pml [BSZ * NUM_KV * GROUP * NCHUNK * 2];

// packed fp32x2 ops (Blackwell)
__device__ __forceinline__ void fma2(unsigned long long& d,
                                     unsigned long long a,
                                     unsigned long long b) {
    asm("fma.rn.f32x2 %0, %1, %2, %0;" : "+l"(d) : "l"(a), "l"(b));
}
__device__ __forceinline__ unsigned long long dup2(float v) {
    unsigned long long r;
    asm("mov.b64 %0, {%1, %1};" : "=l"(r) : "f"(v));
    return r;
}

// ---------------------------------------------------------------
// Split-K GEMM: BM=256, 128 threads, 8m x 8b, double-buffered,
// 4 blocks/SM so independent blocks hide each other's sync/load phases.
// part[split][b][m] = sum_{k in split} x[b,k]*W[m,k]
// ---------------------------------------------------------------
__global__ void __launch_bounds__(128, 4)
gemm8x8_kernel(const float* __restrict__ W, const float* __restrict__ x,
               float* __restrict__ part, int M, int K, int nsplit)
{
    __shared__ __align__(16) float Ws[2][GBK][WST];
    __shared__ __align__(16) float Xs[2][GBK][XST];

    const int m0    = blockIdx.x * GBM;
    const int tot   = K / GBK;
    const int tile0 = (blockIdx.y * tot) / nsplit;
    const int tile1 = ((blockIdx.y + 1) * tot) / nsplit;

    const int t   = threadIdx.x;      // 0..127
    const int ty  = t >> 2;           // 0..31 -> rows m0 + ty*8 .. +7
    const int tx  = t & 3;            // batches tx*8 .. +7
    const int r0  = t >> 1;           // W load base row (0..63), +64 per i
    const int wkv = t & 1;            // which float4 of the 8-k chunk
    const int xb  = t & 31;           // x load batch (t<64)
    const int xkv = t >> 5;           // 0..1 (t<64)

    float4 wst[4];
    float4 xst;

    // ---- prologue: load tile0 ----
    {
        const float* wp = W + (size_t)(m0 + r0) * K + (size_t)tile0 * GBK + wkv * 4;
        #pragma unroll
        for (int i = 0; i < 4; i++)
            wst[i] = *reinterpret_cast<const float4*>(wp + (size_t)i * 64 * K);
        if (t < 64)
            xst = *reinterpret_cast<const float4*>(x + (size_t)xb * K + (size_t)tile0 * GBK + xkv * 4);

        #pragma unroll
        for (int i = 0; i < 4; i++) {
            int r = r0 + i * 64;
            Ws[0][wkv*4+0][r] = wst[i].x;
            Ws[0][wkv*4+1][r] = wst[i].y;
            Ws[0][wkv*4+2][r] = wst[i].z;
            Ws[0][wkv*4+3][r] = wst[i].w;
        }
        if (t < 64) {
            Xs[0][xkv*4+0][xb] = xst.x;
            Xs[0][xkv*4+1][xb] = xst.y;
            Xs[0][xkv*4+2][xb] = xst.z;
            Xs[0][xkv*4+3][xb] = xst.w;
        }
    }
    __syncthreads();

    unsigned long long acc[4][8];
    #pragma unroll
    for (int i = 0; i < 4; i++)
        #pragma unroll
        for (int j = 0; j < 8; j++) acc[i][j] = 0ull;

    int p = 0;
    for (int tile = tile0; tile < tile1; tile++) {
        const bool has_next = (tile + 1 < tile1);
        if (has_next) {
            const float* wp = W + (size_t)(m0 + r0) * K + (size_t)(tile + 1) * GBK + wkv * 4;
            #pragma unroll
            for (int i = 0; i < 4; i++)
                wst[i] = *reinterpret_cast<const float4*>(wp + (size_t)i * 64 * K);
            if (t < 64)
                xst = *reinterpret_cast<const float4*>(x + (size_t)xb * K + (size_t)(tile + 1) * GBK + xkv * 4);
        }

        #pragma unroll
        for (int k = 0; k < GBK; k++) {
            ulonglong2 w01 = *reinterpret_cast<const ulonglong2*>(&Ws[p][k][ty * 8]);
            ulonglong2 w23 = *reinterpret_cast<const ulonglong2*>(&Ws[p][k][ty * 8 + 4]);
            float4 xa = *reinterpret_cast<const float4*>(&Xs[p][k][tx * 8]);
            float4 xc = *reinterpret_cast<const float4*>(&Xs[p][k][tx * 8 + 4]);
            unsigned long long xd;
            xd = dup2(xa.x);
            fma2(acc[0][0], w01.x, xd); fma2(acc[1][0], w01.y, xd);
            fma2(acc[2][0], w23.x, xd); fma2(acc[3][0], w23.y, xd);
            xd = dup2(xa.y);
            fma2(acc[0][1], w01.x, xd); fma2(acc[1][1], w01.y, xd);
            fma2(acc[2][1], w23.x, xd); fma2(acc[3][1], w23.y, xd);
            xd = dup2(xa.z);
            fma2(acc[0][2], w01.x, xd); fma2(acc[1][2], w01.y, xd);
            fma2(acc[2][2], w23.x, xd); fma2(acc[3][2], w23.y, xd);
            xd = dup2(xa.w);
            fma2(acc[0][3], w01.x, xd); fma2(acc[1][3], w01.y, xd);
            fma2(acc[2][3], w23.x, xd); fma2(acc[3][3], w23.y, xd);
            xd = dup2(xc.x);
            fma2(acc[0][4], w01.x, xd); fma2(acc[1][4], w01.y, xd);
            fma2(acc[2][4], w23.x, xd); fma2(acc[3][4], w23.y, xd);
            xd = dup2(xc.y);
            fma2(acc[0][5], w01.x, xd); fma2(acc[1][5], w01.y, xd);
            fma2(acc[2][5], w23.x, xd); fma2(acc[3][5], w23.y, xd);
            xd = dup2(xc.z);
            fma2(acc[0][6], w01.x, xd); fma2(acc[1][6], w01.y, xd);
            fma2(acc[2][6], w23.x, xd); fma2(acc[3][6], w23.y, xd);
            xd = dup2(xc.w);
            fma2(acc[0][7], w01.x, xd); fma2(acc[1][7], w01.y, xd);
            fma2(acc[2][7], w23.x, xd); fma2(acc[3][7], w23.y, xd);
        }

        if (has_next) {
            int pn = p ^ 1;
            #pragma unroll
            for (int i = 0; i < 4; i++) {
                int r = r0 + i * 64;
                Ws[pn][wkv*4+0][r] = wst[i].x;
                Ws[pn][wkv*4+1][r] = wst[i].y;
                Ws[pn][wkv*4+2][r] = wst[i].z;
                Ws[pn][wkv*4+3][r] = wst[i].w;
            }
            if (t < 64) {
                Xs[pn][xkv*4+0][xb] = xst.x;
                Xs[pn][xkv*4+1][xb] = xst.y;
                Xs[pn][xkv*4+2][xb] = xst.z;
                Xs[pn][xkv*4+3][xb] = xst.w;
            }
        }
        __syncthreads();
        p ^= 1;
    }

    // ---- epilogue: plain vector stores of partials ----
    float* pp = part + (size_t)blockIdx.y * BSZ * M;
    #pragma unroll
    for (int bj = 0; bj < 8; bj++) {
        int b = tx * 8 + bj;
        float* dst = pp + (size_t)b * M + m0 + ty * 8;
        *reinterpret_cast<ulonglong2*>(dst)     = make_ulonglong2(acc[0][bj], acc[1][bj]);
        *reinterpret_cast<ulonglong2*>(dst + 4) = make_ulonglong2(acc[2][bj], acc[3][bj]);
    }
}

// ---------------------------------------------------------------
// reduce partials (unchanged)
// ---------------------------------------------------------------
__global__ void __launch_bounds__(256)
reduce_part_kernel(const float4* __restrict__ part, const float4* __restrict__ bias,
                   float4* __restrict__ out, int M4, int nsplit)
{
    int idx = blockIdx.x * 256 + threadIdx.x;
    if (idx >= BSZ * M4) return;
    const size_t step = (size_t)BSZ * M4;
    float4 a0 = bias ? bias[idx % M4] : make_float4(0.f, 0.f, 0.f, 0.f);
    float4 a1 = make_float4(0.f, 0.f, 0.f, 0.f);
    float4 a2 = a1, a3 = a1;
    int s = 0;
    for (; s + 4 <= nsplit; s += 4) {
        float4 p0 = part[(size_t)(s+0) * step + idx];
        float4 p1 = part[(size_t)(s+1) * step + idx];
        float4 p2 = part[(size_t)(s+2) * step + idx];
        float4 p3 = part[(size_t)(s+3) * step + idx];
        a0.x += p0.x; a0.y += p0.y; a0.z += p0.z; a0.w += p0.w;
        a1.x += p1.x; a1.y += p1.y; a1.z += p1.z; a1.w += p1.w;
        a2.x += p2.x; a2.y += p2.y; a2.z += p2.z; a2.w += p2.w;
        a3.x += p3.x; a3.y += p3.y; a3.z += p3.z; a3.w += p3.w;
    }
    for (; s < nsplit; s++) {
        float4 pv = part[(size_t)s * step + idx];
        a0.x += pv.x; a0.y += pv.y; a0.z += pv.z; a0.w += pv.w;
    }
    a0.x += a1.x + a2.x + a3.x;
    a0.y += a1.y + a2.y + a3.y;
    a0.z += a1.z + a2.z + a3.z;
    a0.w += a1.w + a2.w + a3.w;
    out[idx] = a0;
}

// ---------------------------------------------------------------
// Flash-decode partial: EXACT R6 measured-best version.
// ---------------------------------------------------------------
__global__ void __launch_bounds__(128, 4)
attn_partial_kernel(const float* __restrict__ kvc,
                    const int*   __restrict__ seq_lens,
                    const int*   __restrict__ slot_map)
{
    int b   = blockIdx.z;
    int kvh = blockIdx.y;
    int c   = blockIdx.x;

    int seq   = seq_lens[b];
    int start = c * CHUNK;
    if (start >= seq) return;
    int end  = min(seq, start + CHUNK);
    int slot = slot_map[b];

    int lane = threadIdx.x & 31;
    int warp = threadIdx.x >> 5;   // 0..3

    float qr[GROUP][4];
    #pragma unroll
    for (int g = 0; g < GROUP; g++) {
        float4 q4 = *reinterpret_cast<const float4*>(
            &g_qkv[b * QKV_OUT + (kvh * GROUP + g) * HEAD_DIM + lane * 4]);
        qr[g][0] = q4.x * QSCALE; qr[g][1] = q4.y * QSCALE;
        qr[g][2] = q4.z * QSCALE; qr[g][3] = q4.w * QSCALE;
    }

    float m[GROUP], l[GROUP], o[GROUP][4];
    #pragma unroll
    for (int g = 0; g < GROUP; g++) {
        m[g] = -CUDART_INF_F; l[g] = 0.f;
        o[g][0] = o[g][1] = o[g][2] = o[g][3] = 0.f;
    }

    const size_t VPLANE = (size_t)BSZ * MAX_SEQ * NUM_KV * HEAD_DIM;
    const float* knew = &g_qkv[b * QKV_OUT + NUM_HEADS * HEAD_DIM            + kvh * HEAD_DIM];
    const float* vnew = &g_qkv[b * QKV_OUT + (NUM_HEADS + NUM_KV) * HEAD_DIM + kvh * HEAD_DIM];

    auto ldkv = [&](int s, float4& kk, float4& vv) {
        size_t base = (((size_t)b * MAX_SEQ + s) * NUM_KV + kvh) * HEAD_DIM + lane * 4;
        if (s == slot) {
            kk = *reinterpret_cast<const float4*>(knew + lane * 4);
            vv = *reinterpret_cast<const float4*>(vnew + lane * 4);
        } else {
            kk = *reinterpret_cast<const float4*>(&kvc[base]);
            vv = *reinterpret_cast<const float4*>(&kvc[VPLANE + base]);
        }
    };

    int s = start + warp * 4;
    if (s < end) {
        float4 kc[4], vc[4];
        #pragma unroll
        for (int j = 0; j < 4; j++) { kc[j] = make_float4(0,0,0,0); vc[j] = kc[j]; }
        #pragma unroll
        for (int j = 0; j < 4; j++)
            if (s + j < end) ldkv(s + j, kc[j], vc[j]);

        for (;;) {
            int sn = s + 16;
            bool more = (sn < end);
            float4 kn[4], vn[4];
            if (more) {
                #pragma unroll
                for (int j = 0; j < 4; j++)
                    if (sn + j < end) ldkv(sn + j, kn[j], vn[j]);
            }

            float sc[4][GROUP];
            #pragma unroll
            for (int j = 0; j < 4; j++) {
                #pragma unroll
                for (int g = 0; g < GROUP; g++)
                    sc[j][g] = qr[g][0]*kc[j].x + qr[g][1]*kc[j].y
                             + qr[g][2]*kc[j].z + qr[g][3]*kc[j].w;
            }
            #pragma unroll
            for (int off = 16; off >= 1; off >>= 1) {
                #pragma unroll
                for (int j = 0; j < 4; j++)
                    #pragma unroll
                    for (int g = 0; g < GROUP; g++)
                        sc[j][g] += __shfl_xor_sync(0xffffffffu, sc[j][g], off);
            }
            #pragma unroll
            for (int j = 1; j < 4; j++) {
                if (s + j >= end) {
                    #pragma unroll
                    for (int g = 0; g < GROUP; g++) sc[j][g] = -CUDART_INF_F;
                }
            }

            #pragma unroll
            for (int g = 0; g < GROUP; g++) {
                float mx = fmaxf(fmaxf(sc[0][g], sc[1][g]), fmaxf(sc[2][g], sc[3][g]));
                float p0, p1, p2, p3;
                if (mx <= m[g]) {
                    p0 = exp2f(sc[0][g] - m[g]); p1 = exp2f(sc[1][g] - m[g]);
                    p2 = exp2f(sc[2][g] - m[g]); p3 = exp2f(sc[3][g] - m[g]);
                    l[g] += (p0 + p1) + (p2 + p3);
                } else {
                    float corr = exp2f(m[g] - mx);
                    m[g] = mx;
                    p0 = exp2f(sc[0][g] - mx); p1 = exp2f(sc[1][g] - mx);
                    p2 = exp2f(sc[2][g] - mx); p3 = exp2f(sc[3][g] - mx);
                    l[g] = l[g] * corr + (p0 + p1) + (p2 + p3);
                    o[g][0] *= corr; o[g][1] *= corr; o[g][2] *= corr; o[g][3] *= corr;
                }
                o[g][0] += p0*vc[0].x + p1*vc[1].x + p2*vc[2].x + p3*vc[3].x;
                o[g][1] += p0*vc[0].y + p1*vc[1].y + p2*vc[2].y + p3*vc[3].y;
                o[g][2] += p0*vc[0].z + p1*vc[1].z + p2*vc[2].z + p3*vc[3].z;
                o[g][3] += p0*vc[0].w + p1*vc[1].w + p2*vc[2].w + p3*vc[3].w;
            }

            if (!more) break;
            #pragma unroll
            for (int j = 0; j < 4; j++) { kc[j] = kn[j]; vc[j] = vn[j]; }
            s = sn;
        }
    }

    __shared__ float sm_m[4][GROUP];
    __shared__ float sm_l[4][GROUP];
    __shared__ float sm_o[4][GROUP][HEAD_DIM];

    if (lane == 0) {
        #pragma unroll
        for (int g = 0; g < GROUP; g++) { sm_m[warp][g] = m[g]; sm_l[warp][g] = l[g]; }
    }
    #pragma unroll
    for (int g = 0; g < GROUP; g++) {
        sm_o[warp][g][lane*4+0] = o[g][0];
        sm_o[warp][g][lane*4+1] = o[g][1];
        sm_o[warp][g][lane*4+2] = o[g][2];
        sm_o[warp][g][lane*4+3] = o[g][3];
    }
    __syncthreads();

    {
        int g = warp;
        float M = -CUDART_INF_F;
        #pragma unroll
        for (int w = 0; w < 4; w++) M = fmaxf(M, sm_m[w][g]);
        float L = 0.f, O0 = 0.f, O1 = 0.f, O2 = 0.f, O3 = 0.f;
        #pragma unroll
        for (int w = 0; w < 4; w++) {
            float e = exp2f(sm_m[w][g] - M);
            L  += sm_l[w][g] * e;
            O0 += sm_o[w][g][lane*4+0] * e;
            O1 += sm_o[w][g][lane*4+1] * e;
            O2 += sm_o[w][g][lane*4+2] * e;
            O3 += sm_o[w][g][lane*4+3] * e;
        }
        size_t pidx = (((size_t)b * NUM_KV + kvh) * GROUP + g) * NCHUNK + c;
        *reinterpret_cast<float4*>(&g_po[pidx * HEAD_DIM + lane * 4]) =
            make_float4(O0, O1, O2, O3);
        if (lane == 0) { g_pml[pidx*2] = M; g_pml[pidx*2+1] = L; }
    }
}

// ---------------------------------------------------------------
// Chunk merge (unchanged)
// ---------------------------------------------------------------
__global__ void __launch_bounds__(128)
attn_reduce_kernel(const int* __restrict__ seq_lens)
{
    int h = blockIdx.x;
    int b = blockIdx.y;
    int d = threadIdx.x;
    int lane = d & 31, warp = d >> 5;
    int seq = seq_lens[b];
    int nch = (seq + CHUNK - 1) / CHUNK;
    int kvh = h >> 2, g = h & 3;

    size_t base = (((size_t)b * NUM_KV + kvh) * GROUP + g) * NCHUNK;

    __shared__ float es[NCHUNK];
    __shared__ float Ls;

    if (warp == 0) {
        float mm = -CUDART_INF_F, ll = 0.f;
        if (lane < nch) {
            float2 ml = *reinterpret_cast<const float2*>(&g_pml[(base + lane) * 2]);
            mm = ml.x; ll = ml.y;
        }
        float M = mm;
        #pragma unroll
        for (int off = 16; off >= 1; off >>= 1)
            M = fmaxf(M, __shfl_xor_sync(0xffffffffu, M, off));
        float e = (lane < nch) ? exp2f(mm - M) : 0.f;
        float le = ll * e;
        #pragma unroll
        for (int off = 16; off >= 1; off >>= 1)
            le += __shfl_xor_sync(0xffffffffu, le, off);
        es[lane] = e;
        if (lane == 0) Ls = le;
    }
    __syncthreads();

    float O0 = 0.f, O1 = 0.f, O2 = 0.f, O3 = 0.f;
    int cc = 0;
    for (; cc + 4 <= nch; cc += 4) {
        O0 += g_po[(base + cc + 0) * HEAD_DIM + d] * es[cc + 0];
        O1 += g_po[(base + cc + 1) * HEAD_DIM + d] * es[cc + 1];
        O2 += g_po[(base + cc + 2) * HEAD_DIM + d] * es[cc + 2];
        O3 += g_po[(base + cc + 3) * HEAD_DIM + d] * es[cc + 3];
    }
    for (; cc < nch; cc++)
        O0 += g_po[(base + cc) * HEAD_DIM + d] * es[cc];

    g_attn[(size_t)b * HIDDEN + h * HEAD_DIM + d] = ((O0 + O1) + (O2 + O3)) / Ls;
}

// ---------------------------------------------------------------
extern "C" void kernel_launch(void* const* d_in, const int* in_sizes, int n_in,
                              void* d_out, int out_size)
{
    const float* hidden = (const float*)d_in[0];
    const float* kvc    = (const float*)d_in[2];
    const int*   slot   = (const int*)  d_in[3];
    const int*   seql   = (const int*)  d_in[4];
    const float* Wqkv   = (const float*)d_in[5];
    const float* bqkv   = (const float*)d_in[6];
    const float* Wo     = (const float*)d_in[7];
    float*       out    = (float*)d_out;

    void *pq = nullptr, *pa = nullptr, *pp = nullptr;
    cudaGetSymbolAddress(&pq, g_qkv);
    cudaGetSymbolAddress(&pa, g_attn);
    cudaGetSymbolAddress(&pp, g_part);
    float* qkv  = (float*)pq;
    float* attn = (float*)pa;
    float* part = (float*)pp;

    // 1) QKV projection: partials + reduce (bias folded into reduce)
    gemm8x8_kernel<<<dim3(QKV_OUT / GBM, QKV_SPLIT), 128>>>(Wqkv, hidden, part, QKV_OUT, HIDDEN, QKV_SPLIT);
    reduce_part_kernel<<<(BSZ * QKV_OUT / 4 + 255) / 256, 256>>>(
        (const float4*)part, (const float4*)bqkv, (float4*)qkv, QKV_OUT / 4, QKV_SPLIT);

    // 2) flash-decode partials (R6 measured-best)
    attn_partial_kernel<<<dim3(NCHUNK, NUM_KV, BSZ), 128>>>(kvc, seql, slot);

    // 3) merge partials
    attn_reduce_kernel<<<dim3(NUM_HEADS, BSZ), 128>>>(seql);

    // 4) output projection: partials + reduce (writes d_out directly)
    gemm8x8_kernel<<<dim3(HIDDEN / GBM, WO_SPLIT), 128>>>(Wo, attn, part, HIDDEN, HIDDEN, WO_SPLIT);
    reduce_part_kernel<<<(BSZ * HIDDEN / 4 + 255) / 256, 256>>>(
        (const float4*)part, nullptr, (float4*)out, HIDDEN / 4, WO_SPLIT);
}

// round 14
// speedup vs baseline: 1.4808x; 1.0151x over previous
#include <cuda_runtime.h>
#include <math_constants.h>

#define NUM_HEADS 32
#define NUM_KV    8
#define HEAD_DIM  128
#define HIDDEN    4096
#define BSZ       32
#define MAX_SEQ   4096
#define GROUP     4
#define QKV_OUT   6144
#define CHUNK     128
#define NCHUNK    32
// attention scale * log2(e): softmax in exp2 domain
#define QSCALE    (0.08838834764831845f * 1.4426950408889634f)

// GEMM tiling: BM=256, BK=8, 128 threads, per-thread 8m x 8b, 4 blocks/SM
#define GBM 256
#define GBK 8
#define WST 260
#define XST 36
#define QKV_SPLIT 24     // 24 m-blocks x 24 = 576 blocks (~4/SM)
#define WO_SPLIT  36     // 16 m-blocks x 36 = 576 blocks

// ---------------- scratch (no allocs allowed) ----------------
__device__ float g_qkv [BSZ * QKV_OUT];
__device__ float g_attn[BSZ * NUM_HEADS * HEAD_DIM];
__device__ float g_part[QKV_SPLIT * BSZ * QKV_OUT];   // 18.9 MB (= WO_SPLIT*BSZ*HIDDEN)
__device__ float g_po  [BSZ * NUM_KV * GROUP * NCHUNK * HEAD_DIM];
__device__ float g_pml [BSZ * NUM_KV * GROUP * NCHUNK * 2];

// packed fp32x2 ops (Blackwell)
__device__ __forceinline__ void fma2(unsigned long long& d,
                                     unsigned long long a,
                                     unsigned long long b) {
    asm("fma.rn.f32x2 %0, %1, %2, %0;" : "+l"(d) : "l"(a), "l"(b));
}
__device__ __forceinline__ unsigned long long dup2(float v) {
    unsigned long long r;
    asm("mov.b64 %0, {%1, %1};" : "=l"(r) : "f"(v));
    return r;
}

// ---------------------------------------------------------------
// Split-K GEMM: BM=256, 128 threads, 8m x 8b, double-buffered,
// 4 blocks/SM so independent blocks hide each other's sync/load phases.
// part[split][b][m] = sum_{k in split} x[b,k]*W[m,k]
// ---------------------------------------------------------------
__global__ void __launch_bounds__(128, 4)
gemm8x8_kernel(const float* __restrict__ W, const float* __restrict__ x,
               float* __restrict__ part, int M, int K, int nsplit)
{
    __shared__ __align__(16) float Ws[2][GBK][WST];
    __shared__ __align__(16) float Xs[2][GBK][XST];

    const int m0    = blockIdx.x * GBM;
    const int tot   = K / GBK;
    const int tile0 = (blockIdx.y * tot) / nsplit;
    const int tile1 = ((blockIdx.y + 1) * tot) / nsplit;

    const int t   = threadIdx.x;      // 0..127
    const int ty  = t >> 2;           // 0..31 -> rows m0 + ty*8 .. +7
    const int tx  = t & 3;            // batches tx*8 .. +7
    const int r0  = t >> 1;           // W load base row (0..63), +64 per i
    const int wkv = t & 1;            // which float4 of the 8-k chunk
    const int xb  = t & 31;           // x load batch (t<64)
    const int xkv = t >> 5;           // 0..1 (t<64)

    float4 wst[4];
    float4 xst;

    // ---- prologue: load tile0 ----
    {
        const float* wp = W + (size_t)(m0 + r0) * K + (size_t)tile0 * GBK + wkv * 4;
        #pragma unroll
        for (int i = 0; i < 4; i++)
            wst[i] = *reinterpret_cast<const float4*>(wp + (size_t)i * 64 * K);
        if (t < 64)
            xst = *reinterpret_cast<const float4*>(x + (size_t)xb * K + (size_t)tile0 * GBK + xkv * 4);

        #pragma unroll
        for (int i = 0; i < 4; i++) {
            int r = r0 + i * 64;
            Ws[0][wkv*4+0][r] = wst[i].x;
            Ws[0][wkv*4+1][r] = wst[i].y;
            Ws[0][wkv*4+2][r] = wst[i].z;
            Ws[0][wkv*4+3][r] = wst[i].w;
        }
        if (t < 64) {
            Xs[0][xkv*4+0][xb] = xst.x;
            Xs[0][xkv*4+1][xb] = xst.y;
            Xs[0][xkv*4+2][xb] = xst.z;
            Xs[0][xkv*4+3][xb] = xst.w;
        }
    }
    __syncthreads();

    unsigned long long acc[4][8];
    #pragma unroll
    for (int i = 0; i < 4; i++)
        #pragma unroll
        for (int j = 0; j < 8; j++) acc[i][j] = 0ull;

    int p = 0;
    for (int tile = tile0; tile < tile1; tile++) {
        const bool has_next = (tile + 1 < tile1);
        if (has_next) {
            const float* wp = W + (size_t)(m0 + r0) * K + (size_t)(tile + 1) * GBK + wkv * 4;
            #pragma unroll
            for (int i = 0; i < 4; i++)
                wst[i] = *reinterpret_cast<const float4*>(wp + (size_t)i * 64 * K);
            if (t < 64)
                xst = *reinterpret_cast<const float4*>(x + (size_t)xb * K + (size_t)(tile + 1) * GBK + xkv * 4);
        }

        #pragma unroll
        for (int k = 0; k < GBK; k++) {
            ulonglong2 w01 = *reinterpret_cast<const ulonglong2*>(&Ws[p][k][ty * 8]);
            ulonglong2 w23 = *reinterpret_cast<const ulonglong2*>(&Ws[p][k][ty * 8 + 4]);
            float4 xa = *reinterpret_cast<const float4*>(&Xs[p][k][tx * 8]);
            float4 xc = *reinterpret_cast<const float4*>(&Xs[p][k][tx * 8 + 4]);
            unsigned long long xd;
            xd = dup2(xa.x);
            fma2(acc[0][0], w01.x, xd); fma2(acc[1][0], w01.y, xd);
            fma2(acc[2][0], w23.x, xd); fma2(acc[3][0], w23.y, xd);
            xd = dup2(xa.y);
            fma2(acc[0][1], w01.x, xd); fma2(acc[1][1], w01.y, xd);
            fma2(acc[2][1], w23.x, xd); fma2(acc[3][1], w23.y, xd);
            xd = dup2(xa.z);
            fma2(acc[0][2], w01.x, xd); fma2(acc[1][2], w01.y, xd);
            fma2(acc[2][2], w23.x, xd); fma2(acc[3][2], w23.y, xd);
            xd = dup2(xa.w);
            fma2(acc[0][3], w01.x, xd); fma2(acc[1][3], w01.y, xd);
            fma2(acc[2][3], w23.x, xd); fma2(acc[3][3], w23.y, xd);
            xd = dup2(xc.x);
            fma2(acc[0][4], w01.x, xd); fma2(acc[1][4], w01.y, xd);
            fma2(acc[2][4], w23.x, xd); fma2(acc[3][4], w23.y, xd);
            xd = dup2(xc.y);
            fma2(acc[0][5], w01.x, xd); fma2(acc[1][5], w01.y, xd);
            fma2(acc[2][5], w23.x, xd); fma2(acc[3][5], w23.y, xd);
            xd = dup2(xc.z);
            fma2(acc[0][6], w01.x, xd); fma2(acc[1][6], w01.y, xd);
            fma2(acc[2][6], w23.x, xd); fma2(acc[3][6], w23.y, xd);
            xd = dup2(xc.w);
            fma2(acc[0][7], w01.x, xd); fma2(acc[1][7], w01.y, xd);
            fma2(acc[2][7], w23.x, xd); fma2(acc[3][7], w23.y, xd);
        }

        if (has_next) {
            int pn = p ^ 1;
            #pragma unroll
            for (int i = 0; i < 4; i++) {
                int r = r0 + i * 64;
                Ws[pn][wkv*4+0][r] = wst[i].x;
                Ws[pn][wkv*4+1][r] = wst[i].y;
                Ws[pn][wkv*4+2][r] = wst[i].z;
                Ws[pn][wkv*4+3][r] = wst[i].w;
            }
            if (t < 64) {
                Xs[pn][xkv*4+0][xb] = xst.x;
                Xs[pn][xkv*4+1][xb] = xst.y;
                Xs[pn][xkv*4+2][xb] = xst.z;
                Xs[pn][xkv*4+3][xb] = xst.w;
            }
        }
        __syncthreads();
        p ^= 1;
    }

    // ---- epilogue: plain vector stores of partials ----
    float* pp = part + (size_t)blockIdx.y * BSZ * M;
    #pragma unroll
    for (int bj = 0; bj < 8; bj++) {
        int b = tx * 8 + bj;
        float* dst = pp + (size_t)b * M + m0 + ty * 8;
        *reinterpret_cast<ulonglong2*>(dst)     = make_ulonglong2(acc[0][bj], acc[1][bj]);
        *reinterpret_cast<ulonglong2*>(dst + 4) = make_ulonglong2(acc[2][bj], acc[3][bj]);
    }
}

// ---------------------------------------------------------------
// reduce partials (unchanged)
// ---------------------------------------------------------------
__global__ void __launch_bounds__(256)
reduce_part_kernel(const float4* __restrict__ part, const float4* __restrict__ bias,
                   float4* __restrict__ out, int M4, int nsplit)
{
    int idx = blockIdx.x * 256 + threadIdx.x;
    if (idx >= BSZ * M4) return;
    const size_t step = (size_t)BSZ * M4;
    float4 a0 = bias ? bias[idx % M4] : make_float4(0.f, 0.f, 0.f, 0.f);
    float4 a1 = make_float4(0.f, 0.f, 0.f, 0.f);
    float4 a2 = a1, a3 = a1;
    int s = 0;
    for (; s + 4 <= nsplit; s += 4) {
        float4 p0 = part[(size_t)(s+0) * step + idx];
        float4 p1 = part[(size_t)(s+1) * step + idx];
        float4 p2 = part[(size_t)(s+2) * step + idx];
        float4 p3 = part[(size_t)(s+3) * step + idx];
        a0.x += p0.x; a0.y += p0.y; a0.z += p0.z; a0.w += p0.w;
        a1.x += p1.x; a1.y += p1.y; a1.z += p1.z; a1.w += p1.w;
        a2.x += p2.x; a2.y += p2.y; a2.z += p2.z; a2.w += p2.w;
        a3.x += p3.x; a3.y += p3.y; a3.z += p3.z; a3.w += p3.w;
    }
    for (; s < nsplit; s++) {
        float4 pv = part[(size_t)s * step + idx];
        a0.x += pv.x; a0.y += pv.y; a0.z += pv.z; a0.w += pv.w;
    }
    a0.x += a1.x + a2.x + a3.x;
    a0.y += a1.y + a2.y + a3.y;
    a0.z += a1.z + a2.z + a3.z;
    a0.w += a1.w + a2.w + a3.w;
    out[idx] = a0;
}

// ---------------------------------------------------------------
// Flash-decode partial: EXACT R6 measured-best version.
// ---------------------------------------------------------------
__global__ void __launch_bounds__(128, 4)
attn_partial_kernel(const float* __restrict__ kvc,
                    const int*   __restrict__ seq_lens,
                    const int*   __restrict__ slot_map)
{
    int b   = blockIdx.z;
    int kvh = blockIdx.y;
    int c   = blockIdx.x;

    int seq   = seq_lens[b];
    int start = c * CHUNK;
    if (start >= seq) return;
    int end  = min(seq, start + CHUNK);
    int slot = slot_map[b];

    int lane = threadIdx.x & 31;
    int warp = threadIdx.x >> 5;   // 0..3

    float qr[GROUP][4];
    #pragma unroll
    for (int g = 0; g < GROUP; g++) {
        float4 q4 = *reinterpret_cast<const float4*>(
            &g_qkv[b * QKV_OUT + (kvh * GROUP + g) * HEAD_DIM + lane * 4]);
        qr[g][0] = q4.x * QSCALE; qr[g][1] = q4.y * QSCALE;
        qr[g][2] = q4.z * QSCALE; qr[g][3] = q4.w * QSCALE;
    }

    float m[GROUP], l[GROUP], o[GROUP][4];
    #pragma unroll
    for (int g = 0; g < GROUP; g++) {
        m[g] = -CUDART_INF_F; l[g] = 0.f;
        o[g][0] = o[g][1] = o[g][2] = o[g][3] = 0.f;
    }

    const size_t VPLANE = (size_t)BSZ * MAX_SEQ * NUM_KV * HEAD_DIM;
    const float* knew = &g_qkv[b * QKV_OUT + NUM_HEADS * HEAD_DIM            + kvh * HEAD_DIM];
    const float* vnew = &g_qkv[b * QKV_OUT + (NUM_HEADS + NUM_KV) * HEAD_DIM + kvh * HEAD_DIM];

    auto ldkv = [&](int s, float4& kk, float4& vv) {
        size_t base = (((size_t)b * MAX_SEQ + s) * NUM_KV + kvh) * HEAD_DIM + lane * 4;
        if (s == slot) {
            kk = *reinterpret_cast<const float4*>(knew + lane * 4);
            vv = *reinterpret_cast<const float4*>(vnew + lane * 4);
        } else {
            kk = *reinterpret_cast<const float4*>(&kvc[base]);
            vv = *reinterpret_cast<const float4*>(&kvc[VPLANE + base]);
        }
    };

    int s = start + warp * 4;
    if (s < end) {
        float4 kc[4], vc[4];
        #pragma unroll
        for (int j = 0; j < 4; j++) { kc[j] = make_float4(0,0,0,0); vc[j] = kc[j]; }
        #pragma unroll
        for (int j = 0; j < 4; j++)
            if (s + j < end) ldkv(s + j, kc[j], vc[j]);

        for (;;) {
            int sn = s + 16;
            bool more = (sn < end);
            float4 kn[4], vn[4];
            if (more) {
                #pragma unroll
                for (int j = 0; j < 4; j++)
                    if (sn + j < end) ldkv(sn + j, kn[j], vn[j]);
            }

            float sc[4][GROUP];
            #pragma unroll
            for (int j = 0; j < 4; j++) {
                #pragma unroll
                for (int g = 0; g < GROUP; g++)
                    sc[j][g] = qr[g][0]*kc[j].x + qr[g][1]*kc[j].y
                             + qr[g][2]*kc[j].z + qr[g][3]*kc[j].w;
            }
            #pragma unroll
            for (int off = 16; off >= 1; off >>= 1) {
                #pragma unroll
                for (int j = 0; j < 4; j++)
                    #pragma unroll
                    for (int g = 0; g < GROUP; g++)
                        sc[j][g] += __shfl_xor_sync(0xffffffffu, sc[j][g], off);
            }
            #pragma unroll
            for (int j = 1; j < 4; j++) {
                if (s + j >= end) {
                    #pragma unroll
                    for (int g = 0; g < GROUP; g++) sc[j][g] = -CUDART_INF_F;
                }
            }

            #pragma unroll
            for (int g = 0; g < GROUP; g++) {
                float mx = fmaxf(fmaxf(sc[0][g], sc[1][g]), fmaxf(sc[2][g], sc[3][g]));
                float p0, p1, p2, p3;
                if (mx <= m[g]) {
                    p0 = exp2f(sc[0][g] - m[g]); p1 = exp2f(sc[1][g] - m[g]);
                    p2 = exp2f(sc[2][g] - m[g]); p3 = exp2f(sc[3][g] - m[g]);
                    l[g] += (p0 + p1) + (p2 + p3);
                } else {
                    float corr = exp2f(m[g] - mx);
                    m[g] = mx;
                    p0 = exp2f(sc[0][g] - mx); p1 = exp2f(sc[1][g] - mx);
                    p2 = exp2f(sc[2][g] - mx); p3 = exp2f(sc[3][g] - mx);
                    l[g] = l[g] * corr + (p0 + p1) + (p2 + p3);
                    o[g][0] *= corr; o[g][1] *= corr; o[g][2] *= corr; o[g][3] *= corr;
                }
                o[g][0] += p0*vc[0].x + p1*vc[1].x + p2*vc[2].x + p3*vc[3].x;
                o[g][1] += p0*vc[0].y + p1*vc[1].y + p2*vc[2].y + p3*vc[3].y;
                o[g][2] += p0*vc[0].z + p1*vc[1].z + p2*vc[2].z + p3*vc[3].z;
                o[g][3] += p0*vc[0].w + p1*vc[1].w + p2*vc[2].w + p3*vc[3].w;
            }

            if (!more) break;
            #pragma unroll
            for (int j = 0; j < 4; j++) { kc[j] = kn[j]; vc[j] = vn[j]; }
            s = sn;
        }
    }

    __shared__ float sm_m[4][GROUP];
    __shared__ float sm_l[4][GROUP];
    __shared__ float sm_o[4][GROUP][HEAD_DIM];

    if (lane == 0) {
        #pragma unroll
        for (int g = 0; g < GROUP; g++) { sm_m[warp][g] = m[g]; sm_l[warp][g] = l[g]; }
    }
    #pragma unroll
    for (int g = 0; g < GROUP; g++) {
        sm_o[warp][g][lane*4+0] = o[g][0];
        sm_o[warp][g][lane*4+1] = o[g][1];
        sm_o[warp][g][lane*4+2] = o[g][2];
        sm_o[warp][g][lane*4+3] = o[g][3];
    }
    __syncthreads();

    {
        int g = warp;
        float M = -CUDART_INF_F;
        #pragma unroll
        for (int w = 0; w < 4; w++) M = fmaxf(M, sm_m[w][g]);
        float L = 0.f, O0 = 0.f, O1 = 0.f, O2 = 0.f, O3 = 0.f;
        #pragma unroll
        for (int w = 0; w < 4; w++) {
            float e = exp2f(sm_m[w][g] - M);
            L  += sm_l[w][g] * e;
            O0 += sm_o[w][g][lane*4+0] * e;
            O1 += sm_o[w][g][lane*4+1] * e;
            O2 += sm_o[w][g][lane*4+2] * e;
            O3 += sm_o[w][g][lane*4+3] * e;
        }
        size_t pidx = (((size_t)b * NUM_KV + kvh) * GROUP + g) * NCHUNK + c;
        *reinterpret_cast<float4*>(&g_po[pidx * HEAD_DIM + lane * 4]) =
            make_float4(O0, O1, O2, O3);
        if (lane == 0) { g_pml[pidx*2] = M; g_pml[pidx*2+1] = L; }
    }
}

// ---------------------------------------------------------------
// Chunk merge (unchanged)
// ---------------------------------------------------------------
__global__ void __launch_bounds__(128)
attn_reduce_kernel(const int* __restrict__ seq_lens)
{
    int h = blockIdx.x;
    int b = blockIdx.y;
    int d = threadIdx.x;
    int lane = d & 31, warp = d >> 5;
    int seq = seq_lens[b];
    int nch = (seq + CHUNK - 1) / CHUNK;
    int kvh = h >> 2, g = h & 3;

    size_t base = (((size_t)b * NUM_KV + kvh) * GROUP + g) * NCHUNK;

    __shared__ float es[NCHUNK];
    __shared__ float Ls;

    if (warp == 0) {
        float mm = -CUDART_INF_F, ll = 0.f;
        if (lane < nch) {
            float2 ml = *reinterpret_cast<const float2*>(&g_pml[(base + lane) * 2]);
            mm = ml.x; ll = ml.y;
        }
        float M = mm;
        #pragma unroll
        for (int off = 16; off >= 1; off >>= 1)
            M = fmaxf(M, __shfl_xor_sync(0xffffffffu, M, off));
        float e = (lane < nch) ? exp2f(mm - M) : 0.f;
        float le = ll * e;
        #pragma unroll
        for (int off = 16; off >= 1; off >>= 1)
            le += __shfl_xor_sync(0xffffffffu, le, off);
        es[lane] = e;
        if (lane == 0) Ls = le;
    }
    __syncthreads();

    float O0 = 0.f, O1 = 0.f, O2 = 0.f, O3 = 0.f;
    int cc = 0;
    for (; cc + 4 <= nch; cc += 4) {
        O0 += g_po[(base + cc + 0) * HEAD_DIM + d] * es[cc + 0];
        O1 += g_po[(base + cc + 1) * HEAD_DIM + d] * es[cc + 1];
        O2 += g_po[(base + cc + 2) * HEAD_DIM + d] * es[cc + 2];
        O3 += g_po[(base + cc + 3) * HEAD_DIM + d] * es[cc + 3];
    }
    for (; cc < nch; cc++)
        O0 += g_po[(base + cc) * HEAD_DIM + d] * es[cc];

    g_attn[(size_t)b * HIDDEN + h * HEAD_DIM + d] = ((O0 + O1) + (O2 + O3)) / Ls;
}

// ---------------------------------------------------------------
extern "C" void kernel_launch(void* const* d_in, const int* in_sizes, int n_in,
                              void* d_out, int out_size)
{
    const float* hidden = (const float*)d_in[0];
    const float* kvc    = (const float*)d_in[2];
    const int*   slot   = (const int*)  d_in[3];
    const int*   seql   = (const int*)  d_in[4];
    const float* Wqkv   = (const float*)d_in[5];
    const float* bqkv   = (const float*)d_in[6];
    const float* Wo     = (const float*)d_in[7];
    float*       out    = (float*)d_out;

    void *pq = nullptr, *pa = nullptr, *pp = nullptr;
    cudaGetSymbolAddress(&pq, g_qkv);
    cudaGetSymbolAddress(&pa, g_attn);
    cudaGetSymbolAddress(&pp, g_part);
    float* qkv  = (float*)pq;
    float* attn = (float*)pa;
    float* part = (float*)pp;

    // 1) QKV projection: partials + reduce (bias folded into reduce)
    gemm8x8_kernel<<<dim3(QKV_OUT / GBM, QKV_SPLIT), 128>>>(Wqkv, hidden, part, QKV_OUT, HIDDEN, QKV_SPLIT);
    reduce_part_kernel<<<(BSZ * QKV_OUT / 4 + 255) / 256, 256>>>(
        (const float4*)part, (const float4*)bqkv, (float4*)qkv, QKV_OUT / 4, QKV_SPLIT);

    // 2) flash-decode partials (R6 measured-best)
    attn_partial_kernel<<<dim3(NCHUNK, NUM_KV, BSZ), 128>>>(kvc, seql, slot);

    // 3) merge partials
    attn_reduce_kernel<<<dim3(NUM_HEADS, BSZ), 128>>>(seql);

    // 4) output projection: partials + reduce (writes d_out directly)
    gemm8x8_kernel<<<dim3(HIDDEN / GBM, WO_SPLIT), 128>>>(Wo, attn, part, HIDDEN, HIDDEN, WO_SPLIT);
    reduce_part_kernel<<<(BSZ * HIDDEN / 4 + 255) / 256, 256>>>(
        (const float4*)part, nullptr, (float4*)out, HIDDEN / 4, WO_SPLIT);
}

// round 15
// speedup vs baseline: 1.4832x; 1.0016x over previous
#include <cuda_runtime.h>
#include <math_constants.h>

#define NUM_HEADS 32
#define NUM_KV    8
#define HEAD_DIM  128
#define HIDDEN    4096
#define BSZ       32
#define MAX_SEQ   4096
#define GROUP     4
#define QKV_OUT   6144
#define CHUNK     256
#define NCHUNK    16
// attention scale * log2(e): softmax in exp2 domain
#define QSCALE    (0.08838834764831845f * 1.4426950408889634f)

// GEMM tiling: BM=256, BK=8, 128 threads, per-thread 8m x 8b, 4 blocks/SM
#define GBM 256
#define GBK 8
#define WST 260
#define XST 36
#define QKV_SPLIT 24     // 24 m-blocks x 24 = 576 blocks (~4/SM)
#define WO_SPLIT  36     // 16 m-blocks x 36 = 576 blocks

// ---------------- scratch (no allocs allowed) ----------------
__device__ float g_qkv [BSZ * QKV_OUT];
__device__ float g_attn[BSZ * NUM_HEADS * HEAD_DIM];
__device__ float g_part[QKV_SPLIT * BSZ * QKV_OUT];   // 18.9 MB
__device__ float g_po  [BSZ * NUM_KV * GROUP * NCHUNK * HEAD_DIM];  // 8.4 MB
__device__ float g_pml [BSZ * NUM_KV * GROUP * NCHUNK * 2];

// packed fp32x2 ops (Blackwell)
__device__ __forceinline__ void fma2(unsigned long long& d,
                                     unsigned long long a,
                                     unsigned long long b) {
    asm("fma.rn.f32x2 %0, %1, %2, %0;" : "+l"(d) : "l"(a), "l"(b));
}
__device__ __forceinline__ unsigned long long dup2(float v) {
    unsigned long long r;
    asm("mov.b64 %0, {%1, %1};" : "=l"(r) : "f"(v));
    return r;
}

// ---------------------------------------------------------------
// Split-K GEMM (R14 measured form, unchanged)
// ---------------------------------------------------------------
__global__ void __launch_bounds__(128, 4)
gemm8x8_kernel(const float* __restrict__ W, const float* __restrict__ x,
               float* __restrict__ part, int M, int K, int nsplit)
{
    __shared__ __align__(16) float Ws[2][GBK][WST];
    __shared__ __align__(16) float Xs[2][GBK][XST];

    const int m0    = blockIdx.x * GBM;
    const int tot   = K / GBK;
    const int tile0 = (blockIdx.y * tot) / nsplit;
    const int tile1 = ((blockIdx.y + 1) * tot) / nsplit;

    const int t   = threadIdx.x;
    const int ty  = t >> 2;
    const int tx  = t & 3;
    const int r0  = t >> 1;
    const int wkv = t & 1;
    const int xb  = t & 31;
    const int xkv = t >> 5;

    float4 wst[4];
    float4 xst;

    {
        const float* wp = W + (size_t)(m0 + r0) * K + (size_t)tile0 * GBK + wkv * 4;
        #pragma unroll
        for (int i = 0; i < 4; i++)
            wst[i] = *reinterpret_cast<const float4*>(wp + (size_t)i * 64 * K);
        if (t < 64)
            xst = *reinterpret_cast<const float4*>(x + (size_t)xb * K + (size_t)tile0 * GBK + xkv * 4);

        #pragma unroll
        for (int i = 0; i < 4; i++) {
            int r = r0 + i * 64;
            Ws[0][wkv*4+0][r] = wst[i].x;
            Ws[0][wkv*4+1][r] = wst[i].y;
            Ws[0][wkv*4+2][r] = wst[i].z;
            Ws[0][wkv*4+3][r] = wst[i].w;
        }
        if (t < 64) {
            Xs[0][xkv*4+0][xb] = xst.x;
            Xs[0][xkv*4+1][xb] = xst.y;
            Xs[0][xkv*4+2][xb] = xst.z;
            Xs[0][xkv*4+3][xb] = xst.w;
        }
    }
    __syncthreads();

    unsigned long long acc[4][8];
    #pragma unroll
    for (int i = 0; i < 4; i++)
        #pragma unroll
        for (int j = 0; j < 8; j++) acc[i][j] = 0ull;

    int p = 0;
    for (int tile = tile0; tile < tile1; tile++) {
        const bool has_next = (tile + 1 < tile1);
        if (has_next) {
            const float* wp = W + (size_t)(m0 + r0) * K + (size_t)(tile + 1) * GBK + wkv * 4;
            #pragma unroll
            for (int i = 0; i < 4; i++)
                wst[i] = *reinterpret_cast<const float4*>(wp + (size_t)i * 64 * K);
            if (t < 64)
                xst = *reinterpret_cast<const float4*>(x + (size_t)xb * K + (size_t)(tile + 1) * GBK + xkv * 4);
        }

        #pragma unroll
        for (int k = 0; k < GBK; k++) {
            ulonglong2 w01 = *reinterpret_cast<const ulonglong2*>(&Ws[p][k][ty * 8]);
            ulonglong2 w23 = *reinterpret_cast<const ulonglong2*>(&Ws[p][k][ty * 8 + 4]);
            float4 xa = *reinterpret_cast<const float4*>(&Xs[p][k][tx * 8]);
            float4 xc = *reinterpret_cast<const float4*>(&Xs[p][k][tx * 8 + 4]);
            unsigned long long xd;
            xd = dup2(xa.x);
            fma2(acc[0][0], w01.x, xd); fma2(acc[1][0], w01.y, xd);
            fma2(acc[2][0], w23.x, xd); fma2(acc[3][0], w23.y, xd);
            xd = dup2(xa.y);
            fma2(acc[0][1], w01.x, xd); fma2(acc[1][1], w01.y, xd);
            fma2(acc[2][1], w23.x, xd); fma2(acc[3][1], w23.y, xd);
            xd = dup2(xa.z);
            fma2(acc[0][2], w01.x, xd); fma2(acc[1][2], w01.y, xd);
            fma2(acc[2][2], w23.x, xd); fma2(acc[3][2], w23.y, xd);
            xd = dup2(xa.w);
            fma2(acc[0][3], w01.x, xd); fma2(acc[1][3], w01.y, xd);
            fma2(acc[2][3], w23.x, xd); fma2(acc[3][3], w23.y, xd);
            xd = dup2(xc.x);
            fma2(acc[0][4], w01.x, xd); fma2(acc[1][4], w01.y, xd);
            fma2(acc[2][4], w23.x, xd); fma2(acc[3][4], w23.y, xd);
            xd = dup2(xc.y);
            fma2(acc[0][5], w01.x, xd); fma2(acc[1][5], w01.y, xd);
            fma2(acc[2][5], w23.x, xd); fma2(acc[3][5], w23.y, xd);
            xd = dup2(xc.z);
            fma2(acc[0][6], w01.x, xd); fma2(acc[1][6], w01.y, xd);
            fma2(acc[2][6], w23.x, xd); fma2(acc[3][6], w23.y, xd);
            xd = dup2(xc.w);
            fma2(acc[0][7], w01.x, xd); fma2(acc[1][7], w01.y, xd);
            fma2(acc[2][7], w23.x, xd); fma2(acc[3][7], w23.y, xd);
        }

        if (has_next) {
            int pn = p ^ 1;
            #pragma unroll
            for (int i = 0; i < 4; i++) {
                int r = r0 + i * 64;
                Ws[pn][wkv*4+0][r] = wst[i].x;
                Ws[pn][wkv*4+1][r] = wst[i].y;
                Ws[pn][wkv*4+2][r] = wst[i].z;
                Ws[pn][wkv*4+3][r] = wst[i].w;
            }
            if (t < 64) {
                Xs[pn][xkv*4+0][xb] = xst.x;
                Xs[pn][xkv*4+1][xb] = xst.y;
                Xs[pn][xkv*4+2][xb] = xst.z;
                Xs[pn][xkv*4+3][xb] = xst.w;
            }
        }
        __syncthreads();
        p ^= 1;
    }

    float* pp = part + (size_t)blockIdx.y * BSZ * M;
    #pragma unroll
    for (int bj = 0; bj < 8; bj++) {
        int b = tx * 8 + bj;
        float* dst = pp + (size_t)b * M + m0 + ty * 8;
        *reinterpret_cast<ulonglong2*>(dst)     = make_ulonglong2(acc[0][bj], acc[1][bj]);
        *reinterpret_cast<ulonglong2*>(dst + 4) = make_ulonglong2(acc[2][bj], acc[3][bj]);
    }
}

// ---------------------------------------------------------------
// reduce partials: 8-way unrolled with independent accumulators.
// ---------------------------------------------------------------
__global__ void __launch_bounds__(256)
reduce_part_kernel(const float4* __restrict__ part, const float4* __restrict__ bias,
                   float4* __restrict__ out, int M4, int nsplit)
{
    int idx = blockIdx.x * 256 + threadIdx.x;
    if (idx >= BSZ * M4) return;
    const size_t step = (size_t)BSZ * M4;
    float4 a[8];
    a[0] = bias ? bias[idx % M4] : make_float4(0.f, 0.f, 0.f, 0.f);
    #pragma unroll
    for (int i = 1; i < 8; i++) a[i] = make_float4(0.f, 0.f, 0.f, 0.f);
    int s = 0;
    for (; s + 8 <= nsplit; s += 8) {
        #pragma unroll
        for (int i = 0; i < 8; i++) {
            float4 pv = part[(size_t)(s + i) * step + idx];
            a[i].x += pv.x; a[i].y += pv.y; a[i].z += pv.z; a[i].w += pv.w;
        }
    }
    for (; s < nsplit; s++) {
        float4 pv = part[(size_t)s * step + idx];
        a[0].x += pv.x; a[0].y += pv.y; a[0].z += pv.z; a[0].w += pv.w;
    }
    #pragma unroll
    for (int i = 4; i < 8; i++) {
        a[i-4].x += a[i].x; a[i-4].y += a[i].y; a[i-4].z += a[i].z; a[i-4].w += a[i].w;
    }
    a[0].x += a[1].x + a[2].x + a[3].x;
    a[0].y += a[1].y + a[2].y + a[3].y;
    a[0].z += a[1].z + a[2].z + a[3].z;
    a[0].w += a[1].w + a[2].w + a[3].w;
    out[idx] = a[0];
}

// ---------------------------------------------------------------
// Flash-decode partial: R6/R14 measured-best structure (CHUNK=256).
// ---------------------------------------------------------------
__global__ void __launch_bounds__(128, 4)
attn_partial_kernel(const float* __restrict__ kvc,
                    const int*   __restrict__ seq_lens,
                    const int*   __restrict__ slot_map)
{
    int b   = blockIdx.z;
    int kvh = blockIdx.y;
    int c   = blockIdx.x;

    int seq   = seq_lens[b];
    int start = c * CHUNK;
    if (start >= seq) return;
    int end  = min(seq, start + CHUNK);
    int slot = slot_map[b];

    int lane = threadIdx.x & 31;
    int warp = threadIdx.x >> 5;   // 0..3

    float qr[GROUP][4];
    #pragma unroll
    for (int g = 0; g < GROUP; g++) {
        float4 q4 = *reinterpret_cast<const float4*>(
            &g_qkv[b * QKV_OUT + (kvh * GROUP + g) * HEAD_DIM + lane * 4]);
        qr[g][0] = q4.x * QSCALE; qr[g][1] = q4.y * QSCALE;
        qr[g][2] = q4.z * QSCALE; qr[g][3] = q4.w * QSCALE;
    }

    float m[GROUP], l[GROUP], o[GROUP][4];
    #pragma unroll
    for (int g = 0; g < GROUP; g++) {
        m[g] = -CUDART_INF_F; l[g] = 0.f;
        o[g][0] = o[g][1] = o[g][2] = o[g][3] = 0.f;
    }

    const size_t VPLANE = (size_t)BSZ * MAX_SEQ * NUM_KV * HEAD_DIM;
    const float* knew = &g_qkv[b * QKV_OUT + NUM_HEADS * HEAD_DIM            + kvh * HEAD_DIM];
    const float* vnew = &g_qkv[b * QKV_OUT + (NUM_HEADS + NUM_KV) * HEAD_DIM + kvh * HEAD_DIM];

    auto ldkv = [&](int s, float4& kk, float4& vv) {
        size_t base = (((size_t)b * MAX_SEQ + s) * NUM_KV + kvh) * HEAD_DIM + lane * 4;
        if (s == slot) {
            kk = *reinterpret_cast<const float4*>(knew + lane * 4);
            vv = *reinterpret_cast<const float4*>(vnew + lane * 4);
        } else {
            kk = *reinterpret_cast<const float4*>(&kvc[base]);
            vv = *reinterpret_cast<const float4*>(&kvc[VPLANE + base]);
        }
    };

    int s = start + warp * 4;
    if (s < end) {
        float4 kc[4], vc[4];
        #pragma unroll
        for (int j = 0; j < 4; j++) { kc[j] = make_float4(0,0,0,0); vc[j] = kc[j]; }
        #pragma unroll
        for (int j = 0; j < 4; j++)
            if (s + j < end) ldkv(s + j, kc[j], vc[j]);

        for (;;) {
            int sn = s + 16;
            bool more = (sn < end);
            float4 kn[4], vn[4];
            if (more) {
                #pragma unroll
                for (int j = 0; j < 4; j++)
                    if (sn + j < end) ldkv(sn + j, kn[j], vn[j]);
            }

            float sc[4][GROUP];
            #pragma unroll
            for (int j = 0; j < 4; j++) {
                #pragma unroll
                for (int g = 0; g < GROUP; g++)
                    sc[j][g] = qr[g][0]*kc[j].x + qr[g][1]*kc[j].y
                             + qr[g][2]*kc[j].z + qr[g][3]*kc[j].w;
            }
            #pragma unroll
            for (int off = 16; off >= 1; off >>= 1) {
                #pragma unroll
                for (int j = 0; j < 4; j++)
                    #pragma unroll
                    for (int g = 0; g < GROUP; g++)
                        sc[j][g] += __shfl_xor_sync(0xffffffffu, sc[j][g], off);
            }
            #pragma unroll
            for (int j = 1; j < 4; j++) {
                if (s + j >= end) {
                    #pragma unroll
                    for (int g = 0; g < GROUP; g++) sc[j][g] = -CUDART_INF_F;
                }
            }

            #pragma unroll
            for (int g = 0; g < GROUP; g++) {
                float mx = fmaxf(fmaxf(sc[0][g], sc[1][g]), fmaxf(sc[2][g], sc[3][g]));
                float p0, p1, p2, p3;
                if (mx <= m[g]) {
                    p0 = exp2f(sc[0][g] - m[g]); p1 = exp2f(sc[1][g] - m[g]);
                    p2 = exp2f(sc[2][g] - m[g]); p3 = exp2f(sc[3][g] - m[g]);
                    l[g] += (p0 + p1) + (p2 + p3);
                } else {
                    float corr = exp2f(m[g] - mx);
                    m[g] = mx;
                    p0 = exp2f(sc[0][g] - mx); p1 = exp2f(sc[1][g] - mx);
                    p2 = exp2f(sc[2][g] - mx); p3 = exp2f(sc[3][g] - mx);
                    l[g] = l[g] * corr + (p0 + p1) + (p2 + p3);
                    o[g][0] *= corr; o[g][1] *= corr; o[g][2] *= corr; o[g][3] *= corr;
                }
                o[g][0] += p0*vc[0].x + p1*vc[1].x + p2*vc[2].x + p3*vc[3].x;
                o[g][1] += p0*vc[0].y + p1*vc[1].y + p2*vc[2].y + p3*vc[3].y;
                o[g][2] += p0*vc[0].z + p1*vc[1].z + p2*vc[2].z + p3*vc[3].z;
                o[g][3] += p0*vc[0].w + p1*vc[1].w + p2*vc[2].w + p3*vc[3].w;
            }

            if (!more) break;
            #pragma unroll
            for (int j = 0; j < 4; j++) { kc[j] = kn[j]; vc[j] = vn[j]; }
            s = sn;
        }
    }

    __shared__ float sm_m[4][GROUP];
    __shared__ float sm_l[4][GROUP];
    __shared__ float sm_o[4][GROUP][HEAD_DIM];

    if (lane == 0) {
        #pragma unroll
        for (int g = 0; g < GROUP; g++) { sm_m[warp][g] = m[g]; sm_l[warp][g] = l[g]; }
    }
    #pragma unroll
    for (int g = 0; g < GROUP; g++) {
        sm_o[warp][g][lane*4+0] = o[g][0];
        sm_o[warp][g][lane*4+1] = o[g][1];
        sm_o[warp][g][lane*4+2] = o[g][2];
        sm_o[warp][g][lane*4+3] = o[g][3];
    }
    __syncthreads();

    {
        int g = warp;
        float M = -CUDART_INF_F;
        #pragma unroll
        for (int w = 0; w < 4; w++) M = fmaxf(M, sm_m[w][g]);
        float L = 0.f, O0 = 0.f, O1 = 0.f, O2 = 0.f, O3 = 0.f;
        #pragma unroll
        for (int w = 0; w < 4; w++) {
            float e = exp2f(sm_m[w][g] - M);
            L  += sm_l[w][g] * e;
            O0 += sm_o[w][g][lane*4+0] * e;
            O1 += sm_o[w][g][lane*4+1] * e;
            O2 += sm_o[w][g][lane*4+2] * e;
            O3 += sm_o[w][g][lane*4+3] * e;
        }
        size_t pidx = (((size_t)b * NUM_KV + kvh) * GROUP + g) * NCHUNK + c;
        *reinterpret_cast<float4*>(&g_po[pidx * HEAD_DIM + lane * 4]) =
            make_float4(O0, O1, O2, O3);
        if (lane == 0) { g_pml[pidx*2] = M; g_pml[pidx*2+1] = L; }
    }
}

// ---------------------------------------------------------------
// Chunk merge: 8 independent accumulators (latency-bound kernel).
// ---------------------------------------------------------------
__global__ void __launch_bounds__(128)
attn_reduce_kernel(const int* __restrict__ seq_lens)
{
    int h = blockIdx.x;
    int b = blockIdx.y;
    int d = threadIdx.x;
    int lane = d & 31, warp = d >> 5;
    int seq = seq_lens[b];
    int nch = (seq + CHUNK - 1) / CHUNK;
    int kvh = h >> 2, g = h & 3;

    size_t base = (((size_t)b * NUM_KV + kvh) * GROUP + g) * NCHUNK;

    __shared__ float es[NCHUNK];
    __shared__ float Ls;

    if (warp == 0) {
        float mm = -CUDART_INF_F, ll = 0.f;
        if (lane < nch) {
            float2 ml = *reinterpret_cast<const float2*>(&g_pml[(base + lane) * 2]);
            mm = ml.x; ll = ml.y;
        }
        float M = mm;
        #pragma unroll
        for (int off = 16; off >= 1; off >>= 1)
            M = fmaxf(M, __shfl_xor_sync(0xffffffffu, M, off));
        float e = (lane < nch) ? exp2f(mm - M) : 0.f;
        float le = ll * e;
        #pragma unroll
        for (int off = 16; off >= 1; off >>= 1)
            le += __shfl_xor_sync(0xffffffffu, le, off);
        if (lane < NCHUNK) es[lane] = e;
        if (lane == 0) Ls = le;
    }
    __syncthreads();

    float O[8];
    #pragma unroll
    for (int i = 0; i < 8; i++) O[i] = 0.f;
    int cc = 0;
    for (; cc + 8 <= nch; cc += 8) {
        #pragma unroll
        for (int i = 0; i < 8; i++)
            O[i] += g_po[(base + cc + i) * HEAD_DIM + d] * es[cc + i];
    }
    for (; cc < nch; cc++)
        O[0] += g_po[(base + cc) * HEAD_DIM + d] * es[cc];

    float sum = ((O[0] + O[1]) + (O[2] + O[3])) + ((O[4] + O[5]) + (O[6] + O[7]));
    g_attn[(size_t)b * HIDDEN + h * HEAD_DIM + d] = sum / Ls;
}

// ---------------------------------------------------------------
extern "C" void kernel_launch(void* const* d_in, const int* in_sizes, int n_in,
                              void* d_out, int out_size)
{
    const float* hidden = (const float*)d_in[0];
    const float* kvc    = (const float*)d_in[2];
    const int*   slot   = (const int*)  d_in[3];
    const int*   seql   = (const int*)  d_in[4];
    const float* Wqkv   = (const float*)d_in[5];
    const float* bqkv   = (const float*)d_in[6];
    const float* Wo     = (const float*)d_in[7];
    float*       out    = (float*)d_out;

    void *pq = nullptr, *pa = nullptr, *pp = nullptr;
    cudaGetSymbolAddress(&pq, g_qkv);
    cudaGetSymbolAddress(&pa, g_attn);
    cudaGetSymbolAddress(&pp, g_part);
    float* qkv  = (float*)pq;
    float* attn = (float*)pa;
    float* part = (float*)pp;

    // 1) QKV projection: partials + reduce (bias folded into reduce)
    gemm8x8_kernel<<<dim3(QKV_OUT / GBM, QKV_SPLIT), 128>>>(Wqkv, hidden, part, QKV_OUT, HIDDEN, QKV_SPLIT);
    reduce_part_kernel<<<(BSZ * QKV_OUT / 4 + 255) / 256, 256>>>(
        (const float4*)part, (const float4*)bqkv, (float4*)qkv, QKV_OUT / 4, QKV_SPLIT);

    // 2) flash-decode partials (CHUNK=256)
    attn_partial_kernel<<<dim3(NCHUNK, NUM_KV, BSZ), 128>>>(kvc, seql, slot);

    // 3) merge partials
    attn_reduce_kernel<<<dim3(NUM_HEADS, BSZ), 128>>>(seql);

    // 4) output projection: partials + reduce (writes d_out directly)
    gemm8x8_kernel<<<dim3(HIDDEN / GBM, WO_SPLIT), 128>>>(Wo, attn, part, HIDDEN, HIDDEN, WO_SPLIT);
    reduce_part_kernel<<<(BSZ * HIDDEN / 4 + 255) / 256, 256>>>(
        (const float4*)part, nullptr, (float4*)out, HIDDEN / 4, WO_SPLIT);
}